// round 1
// baseline (speedup 1.0000x reference)
#include <cuda_runtime.h>
#include <math.h>

// ---------------- problem constants ----------------
#define Bn   32
#define Sn   128
#define HDn  64
#define NHn  4
#define DHn  16
#define NENCn 2
#define En   8
#define NLn  4
#define CHn  32
#define M1n  16
#define M2n  16
#define Hn   128
#define Wn   128
#define PCHn 128
#define KXn  32     // kept kx rows: 0..15 and 112..127
#define KYn  16     // kept ky cols: 0..15

// ---------------- device scratch (static, no allocation) ----------------
__device__ float  g_h  [Bn*Sn*HDn];        // router hidden
__device__ float  g_qkv[Bn*Sn*3*HDn];      // router qkv
__device__ float  g_att[Bn*Sn*HDn];        // router attention out
__device__ int    g_idx[Bn];               // selected expert per sample
__device__ float  g_v   [Bn*CHn*Hn*Wn];    // FNO activation (64 MB)
__device__ float  g_spec[Bn*CHn*Hn*Wn];    // spectral branch result (64 MB)
__device__ float2 g_X[Bn*KXn*KYn*CHn];     // fwd DFT coeffs  [b][kx][ky][c]
__device__ float2 g_Y[Bn*CHn*KXn*KYn];     // mixed coeffs    [b][o][kx][ky]

__device__ __forceinline__ float gelu_tanh(float x) {
    float x3 = x*x*x;
    return 0.5f*x*(1.0f + tanhf(0.7978845608028654f*(x + 0.044715f*x3)));
}

// ========================= ROUTER =========================

// h[b][s][d] = x[b,0,0,s]*enc_in_w[0,d] + enc_in_b[d]
__global__ void k_encode(const float* __restrict__ x,
                         const float* __restrict__ w,
                         const float* __restrict__ b) {
    int i = blockIdx.x*blockDim.x + threadIdx.x;
    const int tot = Bn*Sn*HDn;
    for (; i < tot; i += gridDim.x*blockDim.x) {
        int d = i & 63;
        int s = (i >> 6) & 127;
        int bb = i >> 13;
        g_h[i] = x[bb*(Hn*Wn) + s]*w[d] + b[d];
    }
}

// qkv = h @ qkv_w[l] + qkv_b[l]   (4096 x 192, K=64)
__global__ void k_qkv(const float* __restrict__ qw,
                      const float* __restrict__ qb, int l) {
    __shared__ float hs[16*64];
    int row0 = blockIdx.x*16;
    for (int p = threadIdx.x; p < 16*64; p += 256) hs[p] = g_h[row0*64 + p];
    __syncthreads();
    const float* wl = qw + l*64*192;
    const float* bl = qb + l*192;
    for (int p = threadIdx.x; p < 16*192; p += 256) {
        int r = p/192, j = p - r*192;
        float acc = bl[j];
        #pragma unroll
        for (int d = 0; d < 64; d++) acc += hs[r*64+d]*wl[d*192+j];
        g_qkv[(row0+r)*192 + j] = acc;
    }
}

// single-pass (flash-style) attention; block = (b, head), 128 threads (one per query row)
__global__ void k_attn() {
    __shared__ float qs[128*16], ks[128*16], vs[128*16];
    int b = blockIdx.x >> 2, hd = blockIdx.x & 3;
    int i = threadIdx.x; // 128
    {
        const float* base = g_qkv + (b*128+i)*192 + hd*16;
        #pragma unroll
        for (int d = 0; d < 16; d++) {
            qs[i*16+d] = base[d];
            ks[i*16+d] = base[64+d];
            vs[i*16+d] = base[128+d];
        }
    }
    __syncthreads();
    float m = -1e30f, ssum = 0.f;
    float out[16];
    #pragma unroll
    for (int d = 0; d < 16; d++) out[d] = 0.f;
    for (int j = 0; j < 128; j++) {
        float s = 0.f;
        #pragma unroll
        for (int d = 0; d < 16; d++) s += qs[i*16+d]*ks[j*16+d];
        s *= 0.25f;                       // 1/sqrt(16)
        float mn = fmaxf(m, s);
        float corr = __expf(m - mn);
        float wj = __expf(s - mn);
        ssum = ssum*corr + wj;
        #pragma unroll
        for (int d = 0; d < 16; d++) out[d] = out[d]*corr + wj*vs[j*16+d];
        m = mn;
    }
    float inv = 1.0f/ssum;
    float* ob = g_att + (b*128+i)*64 + hd*16;
    #pragma unroll
    for (int d = 0; d < 16; d++) ob[d] = out[d]*inv;
}

// h = LN(h + att@ao_w[l] + ao_b[l])
__global__ void k_proj_ln(const float* __restrict__ aw, const float* __restrict__ ab,
                          const float* __restrict__ lns, const float* __restrict__ lnb, int l) {
    __shared__ float as_[16*64];
    __shared__ float ts [16*64];
    int row0 = blockIdx.x*16;
    for (int p = threadIdx.x; p < 1024; p += 256) as_[p] = g_att[row0*64 + p];
    __syncthreads();
    const float* wl = aw + l*64*64;
    for (int p = threadIdx.x; p < 1024; p += 256) {
        int r = p >> 6, d = p & 63;
        float acc = g_h[(row0+r)*64 + d] + ab[l*64 + d];
        #pragma unroll
        for (int e = 0; e < 64; e++) acc += as_[r*64+e]*wl[e*64+d];
        ts[p] = acc;
    }
    __syncthreads();
    if (threadIdx.x < 16) {
        int r = threadIdx.x;
        float mu = 0.f;
        for (int d = 0; d < 64; d++) mu += ts[r*64+d];
        mu *= (1.0f/64.0f);
        float var = 0.f;
        for (int d = 0; d < 64; d++) { float t = ts[r*64+d]-mu; var += t*t; }
        var *= (1.0f/64.0f);
        float rs = rsqrtf(var + 1e-5f);
        for (int d = 0; d < 64; d++)
            g_h[(row0+r)*64+d] = (ts[r*64+d]-mu)*rs*lns[l*64+d] + lnb[l*64+d];
    }
}

// h = LN(h + relu(h@ff1)@ff2)
__global__ void k_ff(const float* __restrict__ w1, const float* __restrict__ b1,
                     const float* __restrict__ w2, const float* __restrict__ b2,
                     const float* __restrict__ lns, const float* __restrict__ lnb, int l) {
    __shared__ float hs [16*64];
    __shared__ float hid[16*256];
    __shared__ float ts [16*64];
    int row0 = blockIdx.x*16;
    for (int p = threadIdx.x; p < 1024; p += 256) hs[p] = g_h[row0*64 + p];
    __syncthreads();
    const float* W1 = w1 + l*64*256;
    for (int p = threadIdx.x; p < 16*256; p += 256) {
        int r = p >> 8, j = p & 255;
        float acc = b1[l*256 + j];
        #pragma unroll
        for (int d = 0; d < 64; d++) acc += hs[r*64+d]*W1[d*256+j];
        hid[p] = fmaxf(acc, 0.0f);
    }
    __syncthreads();
    const float* W2 = w2 + l*256*64;
    for (int p = threadIdx.x; p < 1024; p += 256) {
        int r = p >> 6, d = p & 63;
        float acc = hs[r*64+d] + b2[l*64 + d];
        for (int j = 0; j < 256; j++) acc += hid[r*256+j]*W2[j*64+d];
        ts[p] = acc;
    }
    __syncthreads();
    if (threadIdx.x < 16) {
        int r = threadIdx.x;
        float mu = 0.f;
        for (int d = 0; d < 64; d++) mu += ts[r*64+d];
        mu *= (1.0f/64.0f);
        float var = 0.f;
        for (int d = 0; d < 64; d++) { float t = ts[r*64+d]-mu; var += t*t; }
        var *= (1.0f/64.0f);
        float rs = rsqrtf(var + 1e-5f);
        for (int d = 0; d < 64; d++)
            g_h[(row0+r)*64+d] = (ts[r*64+d]-mu)*rs*lns[l*64+d] + lnb[l*64+d];
    }
}

// feats = mean_s h; logits = feats@fc_w + fc_b; idx = argmax
__global__ void k_head(const float* __restrict__ fcw, const float* __restrict__ fcb) {
    __shared__ float feats[Bn*64];
    for (int p = threadIdx.x; p < Bn*64; p += blockDim.x) {
        int b = p >> 6, d = p & 63;
        float acc = 0.f;
        for (int s = 0; s < 128; s++) acc += g_h[(b*128+s)*64 + d];
        feats[p] = acc*(1.0f/128.0f);
    }
    __syncthreads();
    if (threadIdx.x < Bn) {
        int b = threadIdx.x;
        float best = -1e30f; int bi = 0;
        for (int e = 0; e < En; e++) {
            float acc = fcb[e];
            for (int d = 0; d < 64; d++) acc += feats[b*64+d]*fcw[d*En+e];
            if (acc > best) { best = acc; bi = e; }
        }
        g_idx[b] = bi;
    }
}

// ========================= FNO =========================

// v[b][d][h][w] = x[b,0,h,w]*lift_w[e,0,d] + lift_b[e,d]
__global__ void k_lift(const float* __restrict__ x,
                       const float* __restrict__ lw,
                       const float* __restrict__ lb) {
    __shared__ float xr[128];
    __shared__ float ws[32], bs[32];
    int bb = blockIdx.x >> 7, h = blockIdx.x & 127;
    int e = g_idx[bb];
    if (threadIdx.x < 128) xr[threadIdx.x] = x[bb*16384 + h*128 + threadIdx.x];
    if (threadIdx.x < 32) { ws[threadIdx.x] = lw[e*32 + threadIdx.x]; bs[threadIdx.x] = lb[e*32 + threadIdx.x]; }
    __syncthreads();
    for (int p = threadIdx.x; p < 4096; p += 256) {
        int d = p >> 7, w = p & 127;
        g_v[((bb*32+d)*128 + h)*128 + w] = xr[w]*ws[d] + bs[d];
    }
}

// forward partial rfft2 per (b,c): keep kx in {0..15, 112..127}, ky in 0..15
// dynamic smem: vs[16384] + A[2048 float2] + ct[128] + st[128] = 82944 B
__global__ void k_fwd_dft() {
    extern __shared__ float sm[];
    float*  vs = sm;                          // 16384 floats
    float2* A  = (float2*)(sm + 16384);       // 2048 float2
    float*  ct = sm + 16384 + 4096;           // 128
    float*  st = ct + 128;                    // 128
    int bb = blockIdx.x >> 5, c = blockIdx.x & 31;
    const float* vg = g_v + (bb*32 + c)*16384;
    for (int p = threadIdx.x; p < 16384; p += 256) vs[p] = vg[p];
    if (threadIdx.x < 128) {
        float ang = 6.283185307179586f*(float)threadIdx.x/128.0f;
        ct[threadIdx.x] = cosf(ang);
        st[threadIdx.x] = sinf(ang);
    }
    __syncthreads();
    // A[h][ky] = sum_w v[h][w] * e^{-2πi ky w /128}
    for (int p = threadIdx.x; p < 2048; p += 256) {
        int h = p >> 4, ky = p & 15;
        float re = 0.f, im = 0.f;
        const float* vr = vs + h*128;
        for (int w = 0; w < 128; w++) {
            int t = (ky*w) & 127;
            float v = vr[w];
            re += v*ct[t];
            im -= v*st[t];
        }
        A[p] = make_float2(re, im);
    }
    __syncthreads();
    // X[kx][ky] = sum_h A[h][ky] * e^{-2πi kx h /128}
    for (int p = threadIdx.x; p < 512; p += 256) {
        int kxi = p >> 4, ky = p & 15;
        int kx = (kxi < 16) ? kxi : kxi + 96;
        float re = 0.f, im = 0.f;
        for (int h = 0; h < 128; h++) {
            float2 a = A[h*16 + ky];
            int t = (kx*h) & 127;
            float cc = ct[t], ss = st[t];
            re += a.x*cc + a.y*ss;
            im += a.y*cc - a.x*ss;
        }
        g_X[((bb*32 + kxi)*16 + ky)*32 + c] = make_float2(re, im);
    }
}

// per (b, kx): Y[o][ky] = sum_i X[i][ky] * Wc[e,l,r,i,o,kx',ky]
__global__ void k_mix(const float* __restrict__ wr,
                      const float* __restrict__ wi, int l) {
    __shared__ float2 Xs[16*32];   // [ky][i]
    int bb = blockIdx.x >> 5, kxi = blockIdx.x & 31;
    int e = g_idx[bb];
    int r   = (kxi < 16) ? 0 : 1;
    int kxp = (kxi < 16) ? kxi : kxi - 16;
    const float2* src = g_X + ((bb*32 + kxi)*16)*32;
    for (int p = threadIdx.x; p < 512; p += 256) Xs[p] = src[p];
    __syncthreads();
    int base = ((e*4 + l)*2 + r)*(32*32*256);
    const float* wrb = wr + base + kxp*16;
    const float* wib = wi + base + kxp*16;
    for (int p = threadIdx.x; p < 512; p += 256) {
        int o = p >> 4, ky = p & 15;
        float re = 0.f, im = 0.f;
        #pragma unroll 8
        for (int i = 0; i < 32; i++) {
            float2 xv = Xs[ky*32 + i];
            float wre = wrb[i*8192 + o*256 + ky];
            float wim = wib[i*8192 + o*256 + ky];
            re += xv.x*wre - xv.y*wim;
            im += xv.x*wim + xv.y*wre;
        }
        g_Y[((bb*32 + o)*32 + kxi)*16 + ky] = make_float2(re, im);
    }
}

// inverse partial irfft2 per (b,o) -> g_spec
__global__ void k_inv() {
    __shared__ float2 Ys[32*16];   // [kxi][ky]
    __shared__ float2 Z [128*16];  // [h][ky]
    __shared__ float ct[128], st[128];
    int bb = blockIdx.x >> 5, o = blockIdx.x & 31;
    const float2* src = g_Y + ((bb*32 + o)*32)*16;
    for (int p = threadIdx.x; p < 512; p += 256) Ys[p] = src[p];
    if (threadIdx.x < 128) {
        float ang = 6.283185307179586f*(float)threadIdx.x/128.0f;
        ct[threadIdx.x] = cosf(ang);
        st[threadIdx.x] = sinf(ang);
    }
    __syncthreads();
    // Z[h][ky] = sum_kx Y[kx][ky] e^{+2πi kx h/128}
    for (int p = threadIdx.x; p < 2048; p += 256) {
        int h = p >> 4, ky = p & 15;
        float re = 0.f, im = 0.f;
        #pragma unroll 8
        for (int kxi = 0; kxi < 32; kxi++) {
            float2 y = Ys[kxi*16 + ky];
            int kx = (kxi < 16) ? kxi : kxi + 96;
            int t = (kx*h) & 127;
            float cc = ct[t], ss = st[t];
            re += y.x*cc - y.y*ss;
            im += y.x*ss + y.y*cc;
        }
        Z[p] = make_float2(re, im);
    }
    __syncthreads();
    // spec[h][w] = (1/16384)*(Z[h][0].re + 2*sum_{ky>=1} Re(Z[h][ky] e^{+2πi ky w/128}))
    float* dst = g_spec + (bb*32 + o)*16384;
    for (int p = threadIdx.x; p < 16384; p += 256) {
        int h = p >> 7, w = p & 127;
        const float2* zr = Z + h*16;
        float acc = zr[0].x;
        #pragma unroll
        for (int ky = 1; ky < 16; ky++) {
            int t = (ky*w) & 127;
            acc += 2.0f*(zr[ky].x*ct[t] - zr[ky].y*st[t]);
        }
        dst[p] = acc*(1.0f/16384.0f);
    }
}

// v = [gelu]( spec + v @ skip_w[e,l] + skip_b[e,l] )   in-place, per (b,h) row
__global__ void k_combine(const float* __restrict__ sw,
                          const float* __restrict__ sb, int l) {
    __shared__ float vs[32*128];
    __shared__ float ws[32*32];
    __shared__ float bs[32];
    int bb = blockIdx.x >> 7, h = blockIdx.x & 127;
    int e = g_idx[bb];
    for (int p = threadIdx.x; p < 4096; p += 256) {
        int i = p >> 7, w = p & 127;
        vs[p] = g_v[((bb*32 + i)*128 + h)*128 + w];
    }
    for (int p = threadIdx.x; p < 1024; p += 256) ws[p] = sw[((e*4 + l)*32)*32 + p];
    if (threadIdx.x < 32) bs[threadIdx.x] = sb[(e*4 + l)*32 + threadIdx.x];
    __syncthreads();
    bool act = (l < NLn - 1);
    for (int p = threadIdx.x; p < 4096; p += 256) {
        int o = p >> 7, w = p & 127;
        float acc = g_spec[((bb*32 + o)*128 + h)*128 + w] + bs[o];
        #pragma unroll 8
        for (int i = 0; i < 32; i++) acc += vs[i*128 + w]*ws[i*32 + o];
        if (act) acc = gelu_tanh(acc);
        g_v[((bb*32 + o)*128 + h)*128 + w] = acc;
    }
}

// out = gelu(v @ p1_w + p1_b) @ p2_w + p2_b, per (b,h) row
// dynamic smem: vs[4096] + w1[4096] + hid[128*129] = 98816 B
__global__ void k_proj(const float* __restrict__ p1w, const float* __restrict__ p1b,
                       const float* __restrict__ p2w, const float* __restrict__ p2b,
                       float* __restrict__ out) {
    extern __shared__ float sm[];
    float* vs  = sm;            // 4096
    float* w1  = sm + 4096;     // 4096
    float* hid = sm + 8192;     // 128*129
    int bb = blockIdx.x >> 7, h = blockIdx.x & 127;
    int e = g_idx[bb];
    for (int p = threadIdx.x; p < 4096; p += 256) {
        int c = p >> 7, w = p & 127;
        vs[p] = g_v[((bb*32 + c)*128 + h)*128 + w];
    }
    for (int p = threadIdx.x; p < 4096; p += 256) w1[p] = p1w[e*4096 + p];
    __syncthreads();
    // 256 threads: hidden channel pch = tid&127, w half = (tid>>7)*64
    int pch = threadIdx.x & 127;
    int w0  = (threadIdx.x >> 7)*64;
    float bias = p1b[e*128 + pch];
    for (int w = w0; w < w0 + 64; w++) {
        float acc = bias;
        #pragma unroll 8
        for (int c = 0; c < 32; c++) acc += vs[c*128 + w]*w1[c*128 + pch];
        hid[pch*129 + w] = gelu_tanh(acc);
    }
    __syncthreads();
    if (threadIdx.x < 128) {
        int w = threadIdx.x;
        float acc = p2b[e];
        for (int p = 0; p < 128; p++) acc += hid[p*129 + w]*p2w[e*128 + p];
        out[bb*16384 + h*128 + w] = acc;
    }
}

// ========================= launch =========================
extern "C" void kernel_launch(void* const* d_in, const int* in_sizes, int n_in,
                              void* d_out, int out_size) {
    const float* x        = (const float*)d_in[0];
    const float* enc_in_w = (const float*)d_in[1];
    const float* enc_in_b = (const float*)d_in[2];
    const float* qkv_w    = (const float*)d_in[3];
    const float* qkv_b    = (const float*)d_in[4];
    const float* ao_w     = (const float*)d_in[5];
    const float* ao_b     = (const float*)d_in[6];
    const float* ln1_s    = (const float*)d_in[7];
    const float* ln1_b    = (const float*)d_in[8];
    const float* ff1_w    = (const float*)d_in[9];
    const float* ff1_b    = (const float*)d_in[10];
    const float* ff2_w    = (const float*)d_in[11];
    const float* ff2_b    = (const float*)d_in[12];
    const float* ln2_s    = (const float*)d_in[13];
    const float* ln2_b    = (const float*)d_in[14];
    const float* fc_w     = (const float*)d_in[15];
    const float* fc_b     = (const float*)d_in[16];
    const float* lift_w   = (const float*)d_in[17];
    const float* lift_b   = (const float*)d_in[18];
    const float* spec_wr  = (const float*)d_in[19];
    const float* spec_wi  = (const float*)d_in[20];
    const float* skip_w   = (const float*)d_in[21];
    const float* skip_b   = (const float*)d_in[22];
    const float* p1_w     = (const float*)d_in[23];
    const float* p1_b     = (const float*)d_in[24];
    const float* p2_w     = (const float*)d_in[25];
    const float* p2_b     = (const float*)d_in[26];

    cudaFuncSetAttribute(k_fwd_dft, cudaFuncAttributeMaxDynamicSharedMemorySize, 82944);
    cudaFuncSetAttribute(k_proj,    cudaFuncAttributeMaxDynamicSharedMemorySize, 98816);

    // ---- router ----
    k_encode<<<256, 256>>>(x, enc_in_w, enc_in_b);
    for (int l = 0; l < NENCn; l++) {
        k_qkv<<<(Bn*Sn)/16, 256>>>(qkv_w, qkv_b, l);
        k_attn<<<Bn*NHn, 128>>>();
        k_proj_ln<<<(Bn*Sn)/16, 256>>>(ao_w, ao_b, ln1_s, ln1_b, l);
        k_ff<<<(Bn*Sn)/16, 256>>>(ff1_w, ff1_b, ff2_w, ff2_b, ln2_s, ln2_b, l);
    }
    k_head<<<1, 1024>>>(fc_w, fc_b);

    // ---- FNO ----
    k_lift<<<Bn*Hn, 256>>>(x, lift_w, lift_b);
    for (int l = 0; l < NLn; l++) {
        k_fwd_dft<<<Bn*CHn, 256, 82944>>>();
        k_mix<<<Bn*KXn, 256>>>(spec_wr, spec_wi, l);
        k_inv<<<Bn*CHn, 256>>>();
        k_combine<<<Bn*Hn, 256>>>(skip_w, skip_b, l);
    }
    k_proj<<<Bn*Hn, 256, 98816>>>(p1_w, p1_b, p2_w, p2_b, (float*)d_out);
}

// round 4
// speedup vs baseline: 2.1725x; 2.1725x over previous
#include <cuda_runtime.h>
#include <math.h>

// ---------------- problem constants ----------------
#define Bn   32
#define Sn   128
#define HDn  64
#define NHn  4
#define NENCn 2
#define En   8
#define NLn  4
#define CHn  32
#define M1n  16
#define M2n  16
#define Hn   128
#define Wn   128
#define PCHn 128
#define KXn  32

// ---------------- device scratch ----------------
__device__ float  g_h  [Bn*Sn*HDn];
__device__ float  g_qkv[Bn*Sn*3*HDn];
__device__ float  g_att[Bn*Sn*HDn];
__device__ int    g_idx[Bn];
__device__ float  g_v[Bn*CHn*Hn*Wn];          // 64 MB activation
__device__ float2 g_A[Bn*CHn*Hn*M2n];         // fwd w-DFT coeffs [b][c][h][ky]
__device__ float2 g_X[Bn*KXn*M2n*CHn];        // fwd coeffs [b][kx][ky][c]
__device__ float2 g_Y[Bn*CHn*KXn*M2n];        // mixed [b][o][kx][ky]
__device__ float2 g_Z[Bn*CHn*Hn*M2n];         // inv h-DFT [b][o][h][ky]

__device__ __forceinline__ float gelu_tanh(float x) {
    float x3 = x*x*x;
    float z  = 0.7978845608028654f*(x + 0.044715f*x3);
    // tanh(z) = 1 - 2/(e^{2z}+1)  (safe at both tails)
    float t  = 1.0f - 2.0f/(__expf(2.0f*z) + 1.0f);
    return 0.5f*x*(1.0f + t);
}

// ========================= ROUTER (unchanged, small) =========================
__global__ void k_encode(const float* __restrict__ x,
                         const float* __restrict__ w,
                         const float* __restrict__ b) {
    int i = blockIdx.x*blockDim.x + threadIdx.x;
    const int tot = Bn*Sn*HDn;
    for (; i < tot; i += gridDim.x*blockDim.x) {
        int d = i & 63;
        int s = (i >> 6) & 127;
        int bb = i >> 13;
        g_h[i] = x[bb*(Hn*Wn) + s]*w[d] + b[d];
    }
}

__global__ void k_qkv(const float* __restrict__ qw,
                      const float* __restrict__ qb, int l) {
    __shared__ float hs[16*64];
    int row0 = blockIdx.x*16;
    for (int p = threadIdx.x; p < 16*64; p += 256) hs[p] = g_h[row0*64 + p];
    __syncthreads();
    const float* wl = qw + l*64*192;
    const float* bl = qb + l*192;
    for (int p = threadIdx.x; p < 16*192; p += 256) {
        int r = p/192, j = p - r*192;
        float acc = bl[j];
        #pragma unroll
        for (int d = 0; d < 64; d++) acc += hs[r*64+d]*wl[d*192+j];
        g_qkv[(row0+r)*192 + j] = acc;
    }
}

__global__ void k_attn() {
    __shared__ float qs[128*16], ks[128*16], vs[128*16];
    int b = blockIdx.x >> 2, hd = blockIdx.x & 3;
    int i = threadIdx.x;
    {
        const float* base = g_qkv + (b*128+i)*192 + hd*16;
        #pragma unroll
        for (int d = 0; d < 16; d++) {
            qs[i*16+d] = base[d];
            ks[i*16+d] = base[64+d];
            vs[i*16+d] = base[128+d];
        }
    }
    __syncthreads();
    float m = -1e30f, ssum = 0.f;
    float out[16];
    #pragma unroll
    for (int d = 0; d < 16; d++) out[d] = 0.f;
    for (int j = 0; j < 128; j++) {
        float s = 0.f;
        #pragma unroll
        for (int d = 0; d < 16; d++) s += qs[i*16+d]*ks[j*16+d];
        s *= 0.25f;
        float mn = fmaxf(m, s);
        float corr = __expf(m - mn);
        float wj = __expf(s - mn);
        ssum = ssum*corr + wj;
        #pragma unroll
        for (int d = 0; d < 16; d++) out[d] = out[d]*corr + wj*vs[j*16+d];
        m = mn;
    }
    float inv = 1.0f/ssum;
    float* ob = g_att + (b*128+i)*64 + hd*16;
    #pragma unroll
    for (int d = 0; d < 16; d++) ob[d] = out[d]*inv;
}

__global__ void k_proj_ln(const float* __restrict__ aw, const float* __restrict__ ab,
                          const float* __restrict__ lns, const float* __restrict__ lnb, int l) {
    __shared__ float as_[16*64];
    __shared__ float ts [16*64];
    int row0 = blockIdx.x*16;
    for (int p = threadIdx.x; p < 1024; p += 256) as_[p] = g_att[row0*64 + p];
    __syncthreads();
    const float* wl = aw + l*64*64;
    for (int p = threadIdx.x; p < 1024; p += 256) {
        int r = p >> 6, d = p & 63;
        float acc = g_h[(row0+r)*64 + d] + ab[l*64 + d];
        #pragma unroll
        for (int e = 0; e < 64; e++) acc += as_[r*64+e]*wl[e*64+d];
        ts[p] = acc;
    }
    __syncthreads();
    if (threadIdx.x < 16) {
        int r = threadIdx.x;
        float mu = 0.f;
        for (int d = 0; d < 64; d++) mu += ts[r*64+d];
        mu *= (1.0f/64.0f);
        float var = 0.f;
        for (int d = 0; d < 64; d++) { float t = ts[r*64+d]-mu; var += t*t; }
        var *= (1.0f/64.0f);
        float rs = rsqrtf(var + 1e-5f);
        for (int d = 0; d < 64; d++)
            g_h[(row0+r)*64+d] = (ts[r*64+d]-mu)*rs*lns[l*64+d] + lnb[l*64+d];
    }
}

__global__ void k_ff(const float* __restrict__ w1, const float* __restrict__ b1,
                     const float* __restrict__ w2, const float* __restrict__ b2,
                     const float* __restrict__ lns, const float* __restrict__ lnb, int l) {
    __shared__ float hs [16*64];
    __shared__ float hid[16*256];
    __shared__ float ts [16*64];
    int row0 = blockIdx.x*16;
    for (int p = threadIdx.x; p < 1024; p += 256) hs[p] = g_h[row0*64 + p];
    __syncthreads();
    const float* W1 = w1 + l*64*256;
    for (int p = threadIdx.x; p < 16*256; p += 256) {
        int r = p >> 8, j = p & 255;
        float acc = b1[l*256 + j];
        #pragma unroll
        for (int d = 0; d < 64; d++) acc += hs[r*64+d]*W1[d*256+j];
        hid[p] = fmaxf(acc, 0.0f);
    }
    __syncthreads();
    const float* W2 = w2 + l*256*64;
    for (int p = threadIdx.x; p < 1024; p += 256) {
        int r = p >> 6, d = p & 63;
        float acc = hs[r*64+d] + b2[l*64 + d];
        for (int j = 0; j < 256; j++) acc += hid[r*256+j]*W2[j*64+d];
        ts[p] = acc;
    }
    __syncthreads();
    if (threadIdx.x < 16) {
        int r = threadIdx.x;
        float mu = 0.f;
        for (int d = 0; d < 64; d++) mu += ts[r*64+d];
        mu *= (1.0f/64.0f);
        float var = 0.f;
        for (int d = 0; d < 64; d++) { float t = ts[r*64+d]-mu; var += t*t; }
        var *= (1.0f/64.0f);
        float rs = rsqrtf(var + 1e-5f);
        for (int d = 0; d < 64; d++)
            g_h[(row0+r)*64+d] = (ts[r*64+d]-mu)*rs*lns[l*64+d] + lnb[l*64+d];
    }
}

__global__ void k_head(const float* __restrict__ fcw, const float* __restrict__ fcb) {
    __shared__ float feats[Bn*64];
    for (int p = threadIdx.x; p < Bn*64; p += blockDim.x) {
        int b = p >> 6, d = p & 63;
        float acc = 0.f;
        for (int s = 0; s < 128; s++) acc += g_h[(b*128+s)*64 + d];
        feats[p] = acc*(1.0f/128.0f);
    }
    __syncthreads();
    if (threadIdx.x < Bn) {
        int b = threadIdx.x;
        float best = -1e30f; int bi = 0;
        for (int e = 0; e < En; e++) {
            float acc = fcb[e];
            for (int d = 0; d < 64; d++) acc += feats[b*64+d]*fcw[d*En+e];
            if (acc > best) { best = acc; bi = e; }
        }
        g_idx[b] = bi;
    }
}

// ========================= FNO =========================

__global__ void k_lift(const float* __restrict__ x,
                       const float* __restrict__ lw,
                       const float* __restrict__ lb) {
    __shared__ float xr[128];
    __shared__ float ws[32], bs[32];
    int bb = blockIdx.x >> 7, h = blockIdx.x & 127;
    int e = g_idx[bb];
    if (threadIdx.x < 128) xr[threadIdx.x] = x[bb*16384 + h*128 + threadIdx.x];
    if (threadIdx.x < 32) { ws[threadIdx.x] = lw[e*32 + threadIdx.x]; bs[threadIdx.x] = lb[e*32 + threadIdx.x]; }
    __syncthreads();
    for (int p = threadIdx.x; p < 4096; p += 256) {
        int d = p >> 7, w = p & 127;
        g_v[((bb*32+d)*128 + h)*128 + w] = xr[w]*ws[d] + bs[d];
    }
}

// -------- fwd DFT along w: A[b,c,h,ky] = sum_w v[h,w] e^{-2pi i ky w/128} --------
// block = (b, channel-pair). 256 rows (2c x 128h) x 16 ky complex. K-tiled GEMM.
__global__ __launch_bounds__(256) void k_dft_w() {
    __shared__ float As[256*17];       // [row][k] pitch 17
    __shared__ float ct[128], st[128];
    int bb = blockIdx.x >> 4, c0 = (blockIdx.x & 15)*2;
    int tid = threadIdx.x;
    int ty = tid >> 3;                 // 0..31 (row group)
    int tx = tid & 7;                  // 0..7  (ky group)
    int ky0 = tx*2, ky1 = tx*2 + 1;
    if (tid < 128) {
        float ang = 6.283185307179586f*(float)tid/128.0f;
        ct[tid] = cosf(ang);
        st[tid] = sinf(ang);
    }
    float re0[8], im0[8], re1[8], im1[8];
    #pragma unroll
    for (int i = 0; i < 8; i++) { re0[i]=im0[i]=re1[i]=im1[i]=0.f; }

    const float* vbase = g_v + (bb*32 + c0)*16384;
    for (int kt = 0; kt < 8; kt++) {
        int w0 = kt*16;
        __syncthreads();
        // load tile As[256][16] (row = c_local*128+h) via float4
        #pragma unroll
        for (int j = 0; j < 4; j++) {
            int p = tid + 256*j;           // float4 index over 1024
            int row = p >> 2, q = p & 3;
            const float4 vv = *(const float4*)(vbase + row*128 + w0 + q*4);
            float* dst = As + row*17 + q*4;
            dst[0]=vv.x; dst[1]=vv.y; dst[2]=vv.z; dst[3]=vv.w;
        }
        __syncthreads();
        #pragma unroll
        for (int k = 0; k < 16; k++) {
            int w = w0 + k;
            float c0_ = ct[(ky0*w) & 127], s0_ = st[(ky0*w) & 127];
            float c1_ = ct[(ky1*w) & 127], s1_ = st[(ky1*w) & 127];
            #pragma unroll
            for (int i = 0; i < 8; i++) {
                float v = As[(ty + 32*i)*17 + k];
                re0[i] += v*c0_; im0[i] -= v*s0_;
                re1[i] += v*c1_; im1[i] -= v*s1_;
            }
        }
    }
    #pragma unroll
    for (int i = 0; i < 8; i++) {
        int row = ty + 32*i;
        int cl = row >> 7, h = row & 127;
        float2* dst = g_A + ((bb*32 + c0 + cl)*128 + h)*16;
        dst[ky0] = make_float2(re0[i], im0[i]);
        dst[ky1] = make_float2(re1[i], im1[i]);
    }
}

// -------- fwd DFT along h: X[kx][ky] = sum_h A[h][ky] e^{-2pi i kx h/128} --------
__global__ __launch_bounds__(256) void k_dft_h() {
    __shared__ float2 Az[128*16];
    __shared__ float ct[128], st[128];
    int bb = blockIdx.x >> 5, c = blockIdx.x & 31;
    int tid = threadIdx.x;
    const float2* src = g_A + (bb*32 + c)*128*16;
    for (int p = tid; p < 2048; p += 256) Az[p] = src[p];
    if (tid < 128) {
        float ang = 6.283185307179586f*(float)tid/128.0f;
        ct[tid] = cosf(ang);
        st[tid] = sinf(ang);
    }
    __syncthreads();
    int kxi = tid >> 3;
    int ky0 = (tid & 7)*2, ky1 = ky0 + 1;
    int kx = (kxi < 16) ? kxi : kxi + 96;
    float re0=0.f, im0=0.f, re1=0.f, im1=0.f;
    #pragma unroll 4
    for (int h = 0; h < 128; h++) {
        int t = (kx*h) & 127;
        float cc = ct[t], ss = st[t];
        float2 a0 = Az[h*16 + ky0];
        float2 a1 = Az[h*16 + ky1];
        re0 += a0.x*cc + a0.y*ss;  im0 += a0.y*cc - a0.x*ss;
        re1 += a1.x*cc + a1.y*ss;  im1 += a1.y*cc - a1.x*ss;
    }
    float2* dst = g_X + ((bb*32 + kxi)*16)*32 + c;
    dst[ky0*32] = make_float2(re0, im0);
    dst[ky1*32] = make_float2(re1, im1);
}

// -------- spectral mix: Y[o][ky] = sum_i X[i][ky] * Wc[e,l,r,i,o,kx',ky] --------
__global__ __launch_bounds__(256) void k_mix(const float* __restrict__ wr,
                      const float* __restrict__ wi, int l) {
    __shared__ float2 Xs[16*32];
    int bb = blockIdx.x >> 5, kxi = blockIdx.x & 31;
    int e = g_idx[bb];
    int r   = (kxi < 16) ? 0 : 1;
    int kxp = (kxi < 16) ? kxi : kxi - 16;
    const float2* src = g_X + ((bb*32 + kxi)*16)*32;
    for (int p = threadIdx.x; p < 512; p += 256) Xs[p] = src[p];
    __syncthreads();
    int base = ((e*4 + l)*2 + r)*(32*32*256);
    const float* wrb = wr + base + kxp*16;
    const float* wib = wi + base + kxp*16;
    for (int p = threadIdx.x; p < 512; p += 256) {
        int o = p >> 4, ky = p & 15;
        float re = 0.f, im = 0.f;
        #pragma unroll 8
        for (int i = 0; i < 32; i++) {
            float2 xv = Xs[ky*32 + i];
            float wre = wrb[i*8192 + o*256 + ky];
            float wim = wib[i*8192 + o*256 + ky];
            re += xv.x*wre - xv.y*wim;
            im += xv.x*wim + xv.y*wre;
        }
        g_Y[((bb*32 + o)*32 + kxi)*16 + ky] = make_float2(re, im);
    }
}

// -------- inv DFT along h: Z[h][ky] = sum_kx Y[kx][ky] e^{+2pi i kx h/128} --------
__global__ __launch_bounds__(256) void k_idft_h() {
    __shared__ float2 Ys[32*16];
    __shared__ float ct[128], st[128];
    int bb = blockIdx.x >> 5, o = blockIdx.x & 31;
    int tid = threadIdx.x;
    const float2* src = g_Y + ((bb*32 + o)*32)*16;
    for (int p = tid; p < 512; p += 256) Ys[p] = src[p];
    if (tid < 128) {
        float ang = 6.283185307179586f*(float)tid/128.0f;
        ct[tid] = cosf(ang);
        st[tid] = sinf(ang);
    }
    __syncthreads();
    int hg = tid >> 3;                  // 0..31
    int ky0 = (tid & 7)*2, ky1 = ky0 + 1;
    float re0[4], im0[4], re1[4], im1[4];
    #pragma unroll
    for (int i = 0; i < 4; i++) { re0[i]=im0[i]=re1[i]=im1[i]=0.f; }
    #pragma unroll 4
    for (int kxi = 0; kxi < 32; kxi++) {
        int kx = (kxi < 16) ? kxi : kxi + 96;
        float2 y0 = Ys[kxi*16 + ky0];
        float2 y1 = Ys[kxi*16 + ky1];
        #pragma unroll
        for (int i = 0; i < 4; i++) {
            int h = hg + 32*i;
            int t = (kx*h) & 127;
            float cc = ct[t], ss = st[t];
            re0[i] += y0.x*cc - y0.y*ss;  im0[i] += y0.x*ss + y0.y*cc;
            re1[i] += y1.x*cc - y1.y*ss;  im1[i] += y1.x*ss + y1.y*cc;
        }
    }
    #pragma unroll
    for (int i = 0; i < 4; i++) {
        int h = hg + 32*i;
        float2* dst = g_Z + ((bb*32 + o)*128 + h)*16;
        dst[ky0] = make_float2(re0[i], im0[i]);
        dst[ky1] = make_float2(re1[i], im1[i]);
    }
}

// -------- fused: spec (inv DFT along w) + skip conv + bias + gelu --------
// block = (b, h): out[o][w] for o<32, w<128
__global__ __launch_bounds__(256) void k_spec_combine(const float* __restrict__ sw,
                               const float* __restrict__ sb, int l) {
    __shared__ float2 Zs[32*16];       // scaled by 2/16384
    __shared__ float  vs[32*128];
    __shared__ float  ws[32*32];
    __shared__ float  bs[32];
    __shared__ float  ct[128], st[128];
    int bb = blockIdx.x >> 7, h = blockIdx.x & 127;
    int e = g_idx[bb];
    int tid = threadIdx.x;
    const float scale = 2.0f/16384.0f;
    // load Z row (all o, this h)
    for (int p = tid; p < 512; p += 256) {
        int o = p >> 4, ky = p & 15;
        float2 z = g_Z[((bb*32 + o)*128 + h)*16 + ky];
        Zs[p] = make_float2(z.x*scale, z.y*scale);
    }
    // load v row (all i, this h)
    #pragma unroll
    for (int j = 0; j < 4; j++) {
        int p = tid + 256*j;          // float4 index over 1024
        int i = p >> 5, q = p & 31;
        float4 vv = *(const float4*)(g_v + ((bb*32 + i)*128 + h)*128 + q*4);
        float* dst = vs + i*128 + q*4;
        dst[0]=vv.x; dst[1]=vv.y; dst[2]=vv.z; dst[3]=vv.w;
    }
    for (int p = tid; p < 1024; p += 256) ws[p] = sw[(e*4 + l)*1024 + p];
    if (tid < 32) bs[tid] = sb[(e*4 + l)*32 + tid];
    if (tid < 128) {
        float ang = 6.283185307179586f*(float)tid/128.0f;
        ct[tid] = cosf(ang);
        st[tid] = sinf(ang);
    }
    __syncthreads();

    int wg = tid & 31, og = tid >> 5;        // w_j = wg+32j, o_jj = og+8jj
    float acc[4][4];
    #pragma unroll
    for (int jj = 0; jj < 4; jj++)
        #pragma unroll
        for (int j = 0; j < 4; j++)
            acc[jj][j] = 0.5f*Zs[(og + 8*jj)*16 + 0].x;   // ky=0 term (weight 1)
    // spec: ky = 1..15
    #pragma unroll 4
    for (int ky = 1; ky < 16; ky++) {
        float cc[4], ss[4];
        #pragma unroll
        for (int j = 0; j < 4; j++) {
            int t = (ky*(wg + 32*j)) & 127;
            cc[j] = ct[t]; ss[j] = st[t];
        }
        #pragma unroll
        for (int jj = 0; jj < 4; jj++) {
            float2 z = Zs[(og + 8*jj)*16 + ky];
            #pragma unroll
            for (int j = 0; j < 4; j++)
                acc[jj][j] += z.x*cc[j] - z.y*ss[j];
        }
    }
    // skip: K = 32 channels
    #pragma unroll 4
    for (int i = 0; i < 32; i++) {
        float vv[4], wv[4];
        #pragma unroll
        for (int j = 0; j < 4; j++)  vv[j] = vs[i*128 + wg + 32*j];
        #pragma unroll
        for (int jj = 0; jj < 4; jj++) wv[jj] = ws[i*32 + og + 8*jj];
        #pragma unroll
        for (int jj = 0; jj < 4; jj++)
            #pragma unroll
            for (int j = 0; j < 4; j++)
                acc[jj][j] += vv[j]*wv[jj];
    }
    bool act = (l < NLn - 1);
    #pragma unroll
    for (int jj = 0; jj < 4; jj++) {
        int o = og + 8*jj;
        float bias = bs[o];
        #pragma unroll
        for (int j = 0; j < 4; j++) {
            float val = acc[jj][j] + bias;
            if (act) val = gelu_tanh(val);
            g_v[((bb*32 + o)*128 + h)*128 + wg + 32*j] = val;
        }
    }
}

// -------- projection: out = gelu(v @ p1 + b1) @ p2 + b2 --------
// block = (b, h); register-tiled GEMM 128pch x 128w, K=32
__global__ __launch_bounds__(256, 2) void k_proj2(
                        const float* __restrict__ p1w, const float* __restrict__ p1b,
                        const float* __restrict__ p2w, const float* __restrict__ p2b,
                        float* __restrict__ out) {
    __shared__ float vs [32*128];
    __shared__ float w1 [32*128];
    __shared__ float red[16*128];
    __shared__ float b1s[128], p2s[128];
    int bb = blockIdx.x >> 7, h = blockIdx.x & 127;
    int e = g_idx[bb];
    int tid = threadIdx.x;
    #pragma unroll
    for (int j = 0; j < 4; j++) {
        int p = tid + 256*j;
        int i = p >> 5, q = p & 31;
        float4 vv = *(const float4*)(g_v + ((bb*32 + i)*128 + h)*128 + q*4);
        float* dst = vs + i*128 + q*4;
        dst[0]=vv.x; dst[1]=vv.y; dst[2]=vv.z; dst[3]=vv.w;
    }
    for (int p = tid; p < 4096; p += 256) w1[p] = p1w[e*4096 + p];
    if (tid < 128) {
        b1s[tid] = p1b[e*128 + tid];
        p2s[tid] = p2w[e*128 + tid];
    }
    __syncthreads();

    int wg = tid & 15, pg = tid >> 4;      // w_j = wg+16j, pch_i = pg+16i
    float acc[8][8];
    #pragma unroll
    for (int i = 0; i < 8; i++)
        #pragma unroll
        for (int j = 0; j < 8; j++) acc[i][j] = 0.f;
    #pragma unroll 2
    for (int c = 0; c < 32; c++) {
        float vv[8], wv[8];
        #pragma unroll
        for (int j = 0; j < 8; j++) vv[j] = vs[c*128 + wg + 16*j];
        #pragma unroll
        for (int i = 0; i < 8; i++) wv[i] = w1[c*128 + pg + 16*i];
        #pragma unroll
        for (int i = 0; i < 8; i++)
            #pragma unroll
            for (int j = 0; j < 8; j++)
                acc[i][j] += vv[j]*wv[i];
    }
    float part[8];
    #pragma unroll
    for (int j = 0; j < 8; j++) part[j] = 0.f;
    #pragma unroll
    for (int i = 0; i < 8; i++) {
        int pch = pg + 16*i;
        float bias = b1s[pch], p2v = p2s[pch];
        #pragma unroll
        for (int j = 0; j < 8; j++)
            part[j] += gelu_tanh(acc[i][j] + bias)*p2v;
    }
    #pragma unroll
    for (int j = 0; j < 8; j++) red[pg*128 + wg + 16*j] = part[j];
    __syncthreads();
    if (tid < 128) {
        int w = tid;
        float o = p2b[e];
        #pragma unroll
        for (int pg2 = 0; pg2 < 16; pg2++) o += red[pg2*128 + w];
        out[bb*16384 + h*128 + w] = o;
    }
}

// ========================= launch =========================
extern "C" void kernel_launch(void* const* d_in, const int* in_sizes, int n_in,
                              void* d_out, int out_size) {
    const float* x        = (const float*)d_in[0];
    const float* enc_in_w = (const float*)d_in[1];
    const float* enc_in_b = (const float*)d_in[2];
    const float* qkv_w    = (const float*)d_in[3];
    const float* qkv_b    = (const float*)d_in[4];
    const float* ao_w     = (const float*)d_in[5];
    const float* ao_b     = (const float*)d_in[6];
    const float* ln1_s    = (const float*)d_in[7];
    const float* ln1_b    = (const float*)d_in[8];
    const float* ff1_w    = (const float*)d_in[9];
    const float* ff1_b    = (const float*)d_in[10];
    const float* ff2_w    = (const float*)d_in[11];
    const float* ff2_b    = (const float*)d_in[12];
    const float* ln2_s    = (const float*)d_in[13];
    const float* ln2_b    = (const float*)d_in[14];
    const float* fc_w     = (const float*)d_in[15];
    const float* fc_b     = (const float*)d_in[16];
    const float* lift_w   = (const float*)d_in[17];
    const float* lift_b   = (const float*)d_in[18];
    const float* spec_wr  = (const float*)d_in[19];
    const float* spec_wi  = (const float*)d_in[20];
    const float* skip_w   = (const float*)d_in[21];
    const float* skip_b   = (const float*)d_in[22];
    const float* p1_w     = (const float*)d_in[23];
    const float* p1_b     = (const float*)d_in[24];
    const float* p2_w     = (const float*)d_in[25];
    const float* p2_b     = (const float*)d_in[26];

    // ---- router ----
    k_encode<<<256, 256>>>(x, enc_in_w, enc_in_b);
    for (int l = 0; l < NENCn; l++) {
        k_qkv<<<(Bn*Sn)/16, 256>>>(qkv_w, qkv_b, l);
        k_attn<<<Bn*NHn, 128>>>();
        k_proj_ln<<<(Bn*Sn)/16, 256>>>(ao_w, ao_b, ln1_s, ln1_b, l);
        k_ff<<<(Bn*Sn)/16, 256>>>(ff1_w, ff1_b, ff2_w, ff2_b, ln2_s, ln2_b, l);
    }
    k_head<<<1, 1024>>>(fc_w, fc_b);

    // ---- FNO ----
    k_lift<<<Bn*Hn, 256>>>(x, lift_w, lift_b);
    for (int l = 0; l < NLn; l++) {
        k_dft_w<<<Bn*CHn/2, 256>>>();
        k_dft_h<<<Bn*CHn, 256>>>();
        k_mix<<<Bn*KXn, 256>>>(spec_wr, spec_wi, l);
        k_idft_h<<<Bn*CHn, 256>>>();
        k_spec_combine<<<Bn*Hn, 256>>>(skip_w, skip_b, l);
    }
    k_proj2<<<Bn*Hn, 256>>>(p1_w, p1_b, p2_w, p2_b, (float*)d_out);
}

// round 6
// speedup vs baseline: 2.2024x; 1.0138x over previous
#include <cuda_runtime.h>
#include <math.h>

// ---------------- problem constants ----------------
#define Bn   32
#define Sn   128
#define HDn  64
#define NHn  4
#define NENCn 2
#define En   8
#define NLn  4
#define CHn  32
#define Hn   128
#define Wn   128
#define PCHn 128
#define KXn  32

// ---------------- device scratch ----------------
__device__ float  g_h  [Bn*Sn*HDn];
__device__ float  g_att[Bn*Sn*HDn];
__device__ int    g_idx[Bn];
__device__ float  g_v[Bn*CHn*Hn*Wn];          // 64 MB activation
__device__ float2 g_FX[Bn*Hn*16];             // w-DFT of x rows
__device__ float2 g_A[Bn*CHn*Hn*16];          // fwd w-DFT coeffs [b][c][h][ky]
__device__ float2 g_X[Bn*KXn*16*CHn];         // fwd coeffs [b][kx][ky][c]
__device__ float2 g_Y[Bn*CHn*KXn*16];         // mixed [b][o][kx][ky]
__device__ float2 g_Z[Bn*CHn*Hn*16];          // inv h-DFT [b][o][h][ky]

__device__ __forceinline__ float gelu_tanh(float x) {
    float x3 = x*x*x;
    float z  = 0.7978845608028654f*(x + 0.044715f*x3);
    float t  = 1.0f - 2.0f/(__expf(2.0f*z) + 1.0f);
    return 0.5f*x*(1.0f + t);
}

// ========================= ROUTER =========================

__global__ void k_encode(const float* __restrict__ x,
                         const float* __restrict__ w,
                         const float* __restrict__ b) {
    int i = blockIdx.x*blockDim.x + threadIdx.x;
    const int tot = Bn*Sn*HDn;
    for (; i < tot; i += gridDim.x*blockDim.x) {
        int d = i & 63;
        int s = (i >> 6) & 127;
        int bb = i >> 13;
        g_h[i] = x[bb*(Hn*Wn) + s]*w[d] + b[d];
    }
}

// fused qkv + flash attention; block = (b, head), 128 threads
__global__ __launch_bounds__(128) void k_attn_qkv(const float* __restrict__ qw,
                                                  const float* __restrict__ qb, int l) {
    __shared__ float hs[128*64];     // 32 KB
    __shared__ float kvs[4096];      // 16 KB: W-slice staging, then ks/vs
    int b = blockIdx.x >> 2, hd = blockIdx.x & 3;
    int i = threadIdx.x;

    // load h[b] (128x64)
    {
        const float4* src = (const float4*)(g_h + b*8192);
        float4* dst = (float4*)hs;
        for (int p = i; p < 2048; p += 128) dst[p] = src[p];
    }
    // stage W slice: Ws[d][c], c<48: cols q(0..15), k(16..31), v(32..47)
    float* Ws = kvs;
    {
        const float* W = qw + l*64*192;
        for (int p = i; p < 3072; p += 128) {
            int d = p/48, c = p - d*48;
            int gc = hd*16 + (c & 15) + (c >> 4)*64;
            Ws[p] = W[d*192 + gc];
        }
    }
    __syncthreads();

    float q[16], kk[16], vv[16];
    {
        const float* qbl = qb + l*192 + hd*16;
        #pragma unroll
        for (int j = 0; j < 16; j++) { q[j]=qbl[j]; kk[j]=qbl[64+j]; vv[j]=qbl[128+j]; }
        for (int d = 0; d < 64; d++) {
            float hv = hs[i*64 + d];
            const float4* wr = (const float4*)(Ws + d*48);
            #pragma unroll
            for (int jj = 0; jj < 4; jj++) {
                float4 wq = wr[jj], wk = wr[4+jj], wv = wr[8+jj];
                q [jj*4+0] += hv*wq.x; q [jj*4+1] += hv*wq.y; q [jj*4+2] += hv*wq.z; q [jj*4+3] += hv*wq.w;
                kk[jj*4+0] += hv*wk.x; kk[jj*4+1] += hv*wk.y; kk[jj*4+2] += hv*wk.z; kk[jj*4+3] += hv*wk.w;
                vv[jj*4+0] += hv*wv.x; vv[jj*4+1] += hv*wv.y; vv[jj*4+2] += hv*wv.z; vv[jj*4+3] += hv*wv.w;
            }
        }
    }
    __syncthreads();          // everyone done reading Ws
    float* ks = kvs;          // 128x16
    float* vs = kvs + 2048;   // 128x16
    #pragma unroll
    for (int j = 0; j < 16; j++) { ks[i*16+j] = kk[j]; vs[i*16+j] = vv[j]; }
    __syncthreads();

    float m = -1e30f, ssum = 0.f;
    float out[16];
    #pragma unroll
    for (int d = 0; d < 16; d++) out[d] = 0.f;
    for (int j = 0; j < 128; j++) {
        float s = 0.f;
        #pragma unroll
        for (int d = 0; d < 16; d++) s += q[d]*ks[j*16+d];
        s *= 0.25f;
        float mn = fmaxf(m, s);
        float corr = __expf(m - mn);
        float wj = __expf(s - mn);
        ssum = ssum*corr + wj;
        #pragma unroll
        for (int d = 0; d < 16; d++) out[d] = out[d]*corr + wj*vs[j*16+d];
        m = mn;
    }
    float inv = 1.0f/ssum;
    float* ob = g_att + (b*128+i)*64 + hd*16;
    #pragma unroll
    for (int d = 0; d < 16; d++) ob[d] = out[d]*inv;
}

// fused: h = LN1(h + att@ao + ab); h = LN2(h + relu(h@W1+b1)@W2 + b2)
__global__ __launch_bounds__(256) void k_plf(
        const float* __restrict__ aw, const float* __restrict__ ab,
        const float* __restrict__ lns, const float* __restrict__ lnb,
        const float* __restrict__ w1, const float* __restrict__ b1,
        const float* __restrict__ w2, const float* __restrict__ b2,
        const float* __restrict__ ln2s, const float* __restrict__ ln2b, int l) {
    __shared__ float as_[1024], ts[1024], hs[1024];
    __shared__ float hid[4096];
    int row0 = blockIdx.x*16;
    int tid = threadIdx.x;
    int warp = tid >> 5, lane = tid & 31;

    for (int p = tid; p < 1024; p += 256) as_[p] = g_att[row0*64 + p];
    __syncthreads();
    const float* wl = aw + l*64*64;
    for (int p = tid; p < 1024; p += 256) {
        int r = p >> 6, d = p & 63;
        float acc = g_h[(row0+r)*64 + d] + ab[l*64 + d];
        #pragma unroll
        for (int e = 0; e < 64; e++) acc += as_[r*64+e]*wl[e*64+d];
        ts[p] = acc;
    }
    __syncthreads();
    // LN1 -> hs (warp per 2 rows)
    {
        const float* s_ = lns + l*64; const float* b_ = lnb + l*64;
        #pragma unroll
        for (int rr = 0; rr < 2; rr++) {
            int r = warp*2 + rr;
            float a = ts[r*64+lane], bv = ts[r*64+32+lane];
            float s = a + bv, qq = a*a + bv*bv;
            #pragma unroll
            for (int off = 16; off > 0; off >>= 1) {
                s  += __shfl_xor_sync(0xffffffff, s,  off);
                qq += __shfl_xor_sync(0xffffffff, qq, off);
            }
            float mu = s*(1.0f/64.0f);
            float var = qq*(1.0f/64.0f) - mu*mu;
            float rs = rsqrtf(var + 1e-5f);
            hs[r*64+lane]    = (a  - mu)*rs*s_[lane]    + b_[lane];
            hs[r*64+32+lane] = (bv - mu)*rs*s_[32+lane] + b_[32+lane];
        }
    }
    __syncthreads();
    // FF1
    const float* W1 = w1 + l*64*256;
    for (int p = tid; p < 4096; p += 256) {
        int r = p >> 8, j = p & 255;
        float acc = b1[l*256 + j];
        #pragma unroll
        for (int d = 0; d < 64; d++) acc += hs[r*64+d]*W1[d*256+j];
        hid[p] = fmaxf(acc, 0.0f);
    }
    __syncthreads();
    // FF2 + residual
    const float* W2 = w2 + l*256*64;
    for (int p = tid; p < 1024; p += 256) {
        int r = p >> 6, d = p & 63;
        float acc = hs[r*64+d] + b2[l*64 + d];
        for (int j = 0; j < 256; j++) acc += hid[r*256+j]*W2[j*64+d];
        ts[p] = acc;
    }
    __syncthreads();
    // LN2 -> g_h
    {
        const float* s_ = ln2s + l*64; const float* b_ = ln2b + l*64;
        #pragma unroll
        for (int rr = 0; rr < 2; rr++) {
            int r = warp*2 + rr;
            float a = ts[r*64+lane], bv = ts[r*64+32+lane];
            float s = a + bv, qq = a*a + bv*bv;
            #pragma unroll
            for (int off = 16; off > 0; off >>= 1) {
                s  += __shfl_xor_sync(0xffffffff, s,  off);
                qq += __shfl_xor_sync(0xffffffff, qq, off);
            }
            float mu = s*(1.0f/64.0f);
            float var = qq*(1.0f/64.0f) - mu*mu;
            float rs = rsqrtf(var + 1e-5f);
            g_h[(row0+r)*64+lane]    = (a  - mu)*rs*s_[lane]    + b_[lane];
            g_h[(row0+r)*64+32+lane] = (bv - mu)*rs*s_[32+lane] + b_[32+lane];
        }
    }
}

__global__ void k_head(const float* __restrict__ fcw, const float* __restrict__ fcb) {
    __shared__ float feats[Bn*64];
    for (int p = threadIdx.x; p < Bn*64; p += blockDim.x) {
        int b = p >> 6, d = p & 63;
        float acc = 0.f;
        for (int s = 0; s < 128; s++) acc += g_h[(b*128+s)*64 + d];
        feats[p] = acc*(1.0f/128.0f);
    }
    __syncthreads();
    if (threadIdx.x < Bn) {
        int b = threadIdx.x;
        float best = -1e30f; int bi = 0;
        for (int e = 0; e < En; e++) {
            float acc = fcb[e];
            for (int d = 0; d < 64; d++) acc += feats[b*64+d]*fcw[d*En+e];
            if (acc > best) { best = acc; bi = e; }
        }
        g_idx[b] = bi;
    }
}

// ========================= FNO =========================

// FX[b][h][ky] = sum_w x[b,h,w] e^{-2pi i ky w/128}; block = (b, h-quarter)
__global__ __launch_bounds__(256) void k_fx(const float* __restrict__ x) {
    __shared__ float xs[32*128];
    __shared__ float ct[128], st[128];
    int bb = blockIdx.x >> 2, hq = blockIdx.x & 3;
    int tid = threadIdx.x;
    const float* src = x + bb*16384 + hq*32*128;
    for (int p = tid; p < 4096; p += 256) xs[p] = src[p];
    if (tid < 128) {
        float ang = 6.283185307179586f*(float)tid/128.0f;
        ct[tid] = cosf(ang); st[tid] = sinf(ang);
    }
    __syncthreads();
    int hl = tid >> 3, kp = tid & 7;
    int ky0 = kp*2, ky1 = kp*2 + 1;
    float r0=0.f,i0=0.f,r1=0.f,i1=0.f;
    const float* xr = xs + hl*128;
    for (int w = 0; w < 128; w++) {
        float v = xr[w];
        int t0 = (ky0*w) & 127, t1 = (ky1*w) & 127;
        r0 += v*ct[t0]; i0 -= v*st[t0];
        r1 += v*ct[t1]; i1 -= v*st[t1];
    }
    float2* dst = g_FX + (bb*128 + hq*32 + hl)*16;
    dst[ky0] = make_float2(r0, i0);
    dst[ky1] = make_float2(r1, i1);
}

// lift + layer-0 A:  v = x*ws+bs ;  A = ws*FX (+128*bs at ky=0)
__global__ __launch_bounds__(128) void k_lift_A(const float* __restrict__ x,
                                                const float* __restrict__ lw,
                                                const float* __restrict__ lb) {
    __shared__ float xr[128];
    __shared__ float ws[32], bs[32];
    __shared__ float2 fx[16];
    int bb = blockIdx.x >> 7, h = blockIdx.x & 127;
    int e = g_idx[bb];
    int tid = threadIdx.x;
    xr[tid] = x[bb*16384 + h*128 + tid];
    if (tid < 32) { ws[tid] = lw[e*32+tid]; bs[tid] = lb[e*32+tid]; }
    if (tid < 16) fx[tid] = g_FX[(bb*128+h)*16 + tid];
    __syncthreads();
    for (int p = tid; p < 4096; p += 128) {
        int d = p >> 7, w = p & 127;
        g_v[((bb*32+d)*128+h)*128 + w] = xr[w]*ws[d] + bs[d];
    }
    for (int p = tid; p < 512; p += 128) {
        int c = p >> 4, ky = p & 15;
        float2 f = fx[ky];
        float2 a = make_float2(ws[c]*f.x, ws[c]*f.y);
        if (ky == 0) a.x += 128.0f*bs[c];
        g_A[((bb*32+c)*128+h)*16 + ky] = a;
    }
}

// fwd DFT along h: X[kx][ky] = sum_h A[h][ky] e^{-2pi i kx h/128}
__global__ __launch_bounds__(256) void k_dft_h() {
    __shared__ float2 Az[128*16];
    __shared__ float ct[128], st[128];
    int bb = blockIdx.x >> 5, c = blockIdx.x & 31;
    int tid = threadIdx.x;
    const float2* src = g_A + (bb*32 + c)*128*16;
    for (int p = tid; p < 2048; p += 256) Az[p] = src[p];
    if (tid < 128) {
        float ang = 6.283185307179586f*(float)tid/128.0f;
        ct[tid] = cosf(ang); st[tid] = sinf(ang);
    }
    __syncthreads();
    int kxi = tid >> 3;
    int ky0 = (tid & 7)*2, ky1 = ky0 + 1;
    int kx = (kxi < 16) ? kxi : kxi + 96;
    float re0=0.f, im0=0.f, re1=0.f, im1=0.f;
    #pragma unroll 4
    for (int h = 0; h < 128; h++) {
        int t = (kx*h) & 127;
        float cc = ct[t], ss = st[t];
        float2 a0 = Az[h*16 + ky0];
        float2 a1 = Az[h*16 + ky1];
        re0 += a0.x*cc + a0.y*ss;  im0 += a0.y*cc - a0.x*ss;
        re1 += a1.x*cc + a1.y*ss;  im1 += a1.y*cc - a1.x*ss;
    }
    float2* dst = g_X + ((bb*32 + kxi)*16)*32 + c;
    dst[ky0*32] = make_float2(re0, im0);
    dst[ky1*32] = make_float2(re1, im1);
}

// spectral mix
__global__ __launch_bounds__(256) void k_mix(const float* __restrict__ wr,
                                             const float* __restrict__ wi, int l) {
    __shared__ float2 Xs[16*32];
    int bb = blockIdx.x >> 5, kxi = blockIdx.x & 31;
    int e = g_idx[bb];
    int r   = (kxi < 16) ? 0 : 1;
    int kxp = (kxi < 16) ? kxi : kxi - 16;
    const float2* src = g_X + ((bb*32 + kxi)*16)*32;
    for (int p = threadIdx.x; p < 512; p += 256) Xs[p] = src[p];
    __syncthreads();
    int base = ((e*4 + l)*2 + r)*(32*32*256);
    const float* wrb = wr + base + kxp*16;
    const float* wib = wi + base + kxp*16;
    for (int p = threadIdx.x; p < 512; p += 256) {
        int o = p >> 4, ky = p & 15;
        float re = 0.f, im = 0.f;
        #pragma unroll 8
        for (int i = 0; i < 32; i++) {
            float2 xv = Xs[ky*32 + i];
            float wre = wrb[i*8192 + o*256 + ky];
            float wim = wib[i*8192 + o*256 + ky];
            re += xv.x*wre - xv.y*wim;
            im += xv.x*wim + xv.y*wre;
        }
        g_Y[((bb*32 + o)*32 + kxi)*16 + ky] = make_float2(re, im);
    }
}

// inv DFT along h
__global__ __launch_bounds__(256) void k_idft_h() {
    __shared__ float2 Ys[32*16];
    __shared__ float ct[128], st[128];
    int bb = blockIdx.x >> 5, o = blockIdx.x & 31;
    int tid = threadIdx.x;
    const float2* src = g_Y + ((bb*32 + o)*32)*16;
    for (int p = tid; p < 512; p += 256) Ys[p] = src[p];
    if (tid < 128) {
        float ang = 6.283185307179586f*(float)tid/128.0f;
        ct[tid] = cosf(ang); st[tid] = sinf(ang);
    }
    __syncthreads();
    int hg = tid >> 3;
    int ky0 = (tid & 7)*2, ky1 = ky0 + 1;
    float re0[4], im0[4], re1[4], im1[4];
    #pragma unroll
    for (int i = 0; i < 4; i++) { re0[i]=im0[i]=re1[i]=im1[i]=0.f; }
    #pragma unroll 4
    for (int kxi = 0; kxi < 32; kxi++) {
        int kx = (kxi < 16) ? kxi : kxi + 96;
        float2 y0 = Ys[kxi*16 + ky0];
        float2 y1 = Ys[kxi*16 + ky1];
        #pragma unroll
        for (int i = 0; i < 4; i++) {
            int h = hg + 32*i;
            int t = (kx*h) & 127;
            float cc = ct[t], ss = st[t];
            re0[i] += y0.x*cc - y0.y*ss;  im0[i] += y0.x*ss + y0.y*cc;
            re1[i] += y1.x*cc - y1.y*ss;  im1[i] += y1.x*ss + y1.y*cc;
        }
    }
    #pragma unroll
    for (int i = 0; i < 4; i++) {
        int h = hg + 32*i;
        float2* dst = g_Z + ((bb*32 + o)*128 + h)*16;
        dst[ky0] = make_float2(re0[i], im0[i]);
        dst[ky1] = make_float2(re1[i], im1[i]);
    }
}

// fused: [irfft-w + skip GEMM as ONE K=63 GEMM] + bias + gelu + next-layer w-DFT
__global__ __launch_bounds__(256) void k_spec_combine(const float* __restrict__ sw,
                                                      const float* __restrict__ sb,
                                                      int l, int last) {
    __shared__ float Bk[63*128];   // rows 0..30 twiddles, 31..62 = v ; reused as outs[32][128]
    __shared__ float Ak[63*32];
    __shared__ float ct[128], st[128];
    __shared__ float bs[32];
    int bb = blockIdx.x >> 7, h = blockIdx.x & 127;
    int e = g_idx[bb];
    int tid = threadIdx.x;

    if (tid < 128) {
        float ang = 6.283185307179586f*(float)tid/128.0f;
        ct[tid] = cosf(ang); st[tid] = sinf(ang);
    }
    // Bk v rows
    for (int p = tid; p < 1024; p += 256) {
        int i = p >> 5, q = p & 31;
        ((float4*)(Bk + (31+i)*128))[q] =
            ((const float4*)(g_v + ((bb*32+i)*128+h)*128))[q];
    }
    // Bk twiddle rows (independent of ct/st table: direct fast sincos)
    for (int p = tid; p < 31*128; p += 256) {
        int k = p >> 7, w = p & 127;
        float val;
        if (k == 0) val = 1.0f;
        else if (k < 16) { int t = (k*w) & 127; val = __cosf(0.0490873852123405f*(float)t); }
        else             { int t = ((k-15)*w) & 127; val = __sinf(0.0490873852123405f*(float)t); }
        Bk[p] = val;
    }
    // Ak Z rows
    for (int p = tid; p < 512; p += 256) {
        int o = p & 31, ky = p >> 5;
        float2 z = g_Z[((bb*32+o)*128+h)*16 + ky];
        const float s2 = 2.0f/16384.0f;
        if (ky == 0) Ak[o] = z.x*(1.0f/16384.0f);
        else { Ak[ky*32+o] = z.x*s2; Ak[(15+ky)*32+o] = -z.y*s2; }
    }
    // Ak skip rows
    for (int p = tid; p < 1024; p += 256)
        Ak[(31 + (p>>5))*32 + (p & 31)] = sw[(e*4+l)*1024 + p];
    if (tid < 32) bs[tid] = sb[(e*4+l)*32 + tid];
    __syncthreads();

    int wg = tid & 31, og = tid >> 5;   // w tile wg*4.., o tile og*4..
    float acc[4][4];
    #pragma unroll
    for (int jj = 0; jj < 4; jj++)
        #pragma unroll
        for (int j = 0; j < 4; j++) acc[jj][j] = 0.f;
    #pragma unroll 7
    for (int k = 0; k < 63; k++) {
        float4 bv = ((const float4*)(Bk + k*128))[wg];
        float4 av = ((const float4*)(Ak + k*32))[og];
        float a0=av.x, a1=av.y, a2=av.z, a3=av.w;
        acc[0][0]+=a0*bv.x; acc[0][1]+=a0*bv.y; acc[0][2]+=a0*bv.z; acc[0][3]+=a0*bv.w;
        acc[1][0]+=a1*bv.x; acc[1][1]+=a1*bv.y; acc[1][2]+=a1*bv.z; acc[1][3]+=a1*bv.w;
        acc[2][0]+=a2*bv.x; acc[2][1]+=a2*bv.y; acc[2][2]+=a2*bv.z; acc[2][3]+=a2*bv.w;
        acc[3][0]+=a3*bv.x; acc[3][1]+=a3*bv.y; acc[3][2]+=a3*bv.z; acc[3][3]+=a3*bv.w;
    }
    // finalize values
    float4 res[4];
    #pragma unroll
    for (int jj = 0; jj < 4; jj++) {
        int o = og*4 + jj;
        float bias = bs[o];
        float v0 = acc[jj][0]+bias, v1 = acc[jj][1]+bias, v2 = acc[jj][2]+bias, v3 = acc[jj][3]+bias;
        if (!last) { v0 = gelu_tanh(v0); v1 = gelu_tanh(v1); v2 = gelu_tanh(v2); v3 = gelu_tanh(v3); }
        res[jj] = make_float4(v0, v1, v2, v3);
    }
    __syncthreads();   // all reads of Bk complete before reuse
    float* outs = Bk;  // [32][128]
    #pragma unroll
    for (int jj = 0; jj < 4; jj++) {
        int o = og*4 + jj;
        ((float4*)(g_v + ((bb*32+o)*128+h)*128))[wg] = res[jj];
        if (!last) ((float4*)(outs + o*128))[wg] = res[jj];
    }
    if (!last) {
        __syncthreads();
        // next-layer w-DFT epilogue: A[c][ky] = sum_w outs[c][w] e^{-2pi i ky w/128}
        int c = tid >> 3;
        int ky0 = (tid & 7)*2, ky1 = ky0 + 1;
        float c0 = 1.f, s0 = 0.f, c1 = 1.f, s1 = 0.f;
        float dc0 = ct[ky0], ds0 = st[ky0];
        float dc1 = ct[ky1], ds1 = st[ky1];
        float r0=0.f,i0=0.f,r1=0.f,i1=0.f;
        const float* orow = outs + c*128;
        for (int w = 0; w < 128; w++) {
            float v = orow[w];
            r0 += v*c0; i0 -= v*s0;
            r1 += v*c1; i1 -= v*s1;
            float nc0 = c0*dc0 - s0*ds0; s0 = c0*ds0 + s0*dc0; c0 = nc0;
            float nc1 = c1*dc1 - s1*ds1; s1 = c1*ds1 + s1*dc1; c1 = nc1;
        }
        float2* dst = g_A + ((bb*32+c)*128+h)*16;
        dst[ky0] = make_float2(r0, i0);
        dst[ky1] = make_float2(r1, i1);
    }
}

// projection with vectorized smem access
__global__ __launch_bounds__(256, 2) void k_proj2(
        const float* __restrict__ p1w, const float* __restrict__ p1b,
        const float* __restrict__ p2w, const float* __restrict__ p2b,
        float* __restrict__ out) {
    __shared__ float vs [32*128];
    __shared__ float w1p[32*128];
    __shared__ float red[16*128];
    __shared__ float b1s[128], p2s[128];
    int bb = blockIdx.x >> 7, h = blockIdx.x & 127;
    int e = g_idx[bb];
    int tid = threadIdx.x;
    #pragma unroll
    for (int j = 0; j < 4; j++) {
        int p = tid + 256*j;
        int i = p >> 5, q = p & 31;
        ((float4*)(vs + i*128))[q] = ((const float4*)(g_v + ((bb*32+i)*128+h)*128))[q];
    }
    for (int p = tid; p < 4096; p += 256) {
        float val = p1w[e*4096 + p];
        int c = p >> 7, pch = p & 127;
        w1p[c*128 + (pch & 15)*8 + (pch >> 4)] = val;
    }
    if (tid < 128) {
        b1s[tid] = p1b[e*128 + tid];
        p2s[tid] = p2w[e*128 + tid];
    }
    __syncthreads();

    int wg = tid & 15, pg = tid >> 4;
    int w0 = wg*8;
    float acc[8][8];
    #pragma unroll
    for (int i = 0; i < 8; i++)
        #pragma unroll
        for (int j = 0; j < 8; j++) acc[i][j] = 0.f;
    #pragma unroll 2
    for (int c = 0; c < 32; c++) {
        float4 v0 = ((const float4*)(vs + c*128 + w0))[0];
        float4 v1 = ((const float4*)(vs + c*128 + w0))[1];
        float4 u0 = ((const float4*)(w1p + c*128 + pg*8))[0];
        float4 u1 = ((const float4*)(w1p + c*128 + pg*8))[1];
        float vv[8] = {v0.x,v0.y,v0.z,v0.w,v1.x,v1.y,v1.z,v1.w};
        float uu[8] = {u0.x,u0.y,u0.z,u0.w,u1.x,u1.y,u1.z,u1.w};
        #pragma unroll
        for (int i = 0; i < 8; i++)
            #pragma unroll
            for (int j = 0; j < 8; j++)
                acc[i][j] += uu[i]*vv[j];
    }
    float part[8];
    #pragma unroll
    for (int j = 0; j < 8; j++) part[j] = 0.f;
    #pragma unroll
    for (int i = 0; i < 8; i++) {
        int pch = pg + 16*i;
        float bias = b1s[pch], p2v = p2s[pch];
        #pragma unroll
        for (int j = 0; j < 8; j++)
            part[j] += gelu_tanh(acc[i][j] + bias)*p2v;
    }
    #pragma unroll
    for (int j = 0; j < 8; j++) red[pg*128 + w0 + j] = part[j];
    __syncthreads();
    if (tid < 128) {
        int w = tid;
        float o = p2b[e];
        #pragma unroll
        for (int pg2 = 0; pg2 < 16; pg2++) o += red[pg2*128 + w];
        out[bb*16384 + h*128 + w] = o;
    }
}

// ========================= launch =========================
extern "C" void kernel_launch(void* const* d_in, const int* in_sizes, int n_in,
                              void* d_out, int out_size) {
    const float* x        = (const float*)d_in[0];
    const float* enc_in_w = (const float*)d_in[1];
    const float* enc_in_b = (const float*)d_in[2];
    const float* qkv_w    = (const float*)d_in[3];
    const float* qkv_b    = (const float*)d_in[4];
    const float* ao_w     = (const float*)d_in[5];
    const float* ao_b     = (const float*)d_in[6];
    const float* ln1_s    = (const float*)d_in[7];
    const float* ln1_b    = (const float*)d_in[8];
    const float* ff1_w    = (const float*)d_in[9];
    const float* ff1_b    = (const float*)d_in[10];
    const float* ff2_w    = (const float*)d_in[11];
    const float* ff2_b    = (const float*)d_in[12];
    const float* ln2_s    = (const float*)d_in[13];
    const float* ln2_b    = (const float*)d_in[14];
    const float* fc_w     = (const float*)d_in[15];
    const float* fc_b     = (const float*)d_in[16];
    const float* lift_w   = (const float*)d_in[17];
    const float* lift_b   = (const float*)d_in[18];
    const float* spec_wr  = (const float*)d_in[19];
    const float* spec_wi  = (const float*)d_in[20];
    const float* skip_w   = (const float*)d_in[21];
    const float* skip_b   = (const float*)d_in[22];
    const float* p1_w     = (const float*)d_in[23];
    const float* p1_b     = (const float*)d_in[24];
    const float* p2_w     = (const float*)d_in[25];
    const float* p2_b     = (const float*)d_in[26];

    // FX of x (independent of router)
    k_fx<<<Bn*4, 256>>>(x);

    // ---- router ----
    k_encode<<<256, 256>>>(x, enc_in_w, enc_in_b);
    for (int l = 0; l < NENCn; l++) {
        k_attn_qkv<<<Bn*NHn, 128>>>(qkv_w, qkv_b, l);
        k_plf<<<(Bn*Sn)/16, 256>>>(ao_w, ao_b, ln1_s, ln1_b,
                                   ff1_w, ff1_b, ff2_w, ff2_b, ln2_s, ln2_b, l);
    }
    k_head<<<1, 1024>>>(fc_w, fc_b);

    // ---- FNO ----
    k_lift_A<<<Bn*Hn, 128>>>(x, lift_w, lift_b);
    for (int l = 0; l < NLn; l++) {
        k_dft_h<<<Bn*CHn, 256>>>();
        k_mix<<<Bn*KXn, 256>>>(spec_wr, spec_wi, l);
        k_idft_h<<<Bn*CHn, 256>>>();
        k_spec_combine<<<Bn*Hn, 256>>>(skip_w, skip_b, l, (l == NLn-1) ? 1 : 0);
    }
    k_proj2<<<Bn*Hn, 256>>>(p1_w, p1_b, p2_w, p2_b, (float*)d_out);
}

// round 8
// speedup vs baseline: 2.2357x; 1.0151x over previous
#include <cuda_runtime.h>
#include <math.h>

// ---------------- problem constants ----------------
#define Bn   32
#define Sn   128
#define HDn  64
#define NHn  4
#define NENCn 2
#define En   8
#define NLn  4
#define CHn  32
#define Hn   128
#define Wn   128
#define PCHn 128
#define KXn  32

// ---------------- device scratch ----------------
__device__ float  g_h  [Bn*Sn*HDn];
__device__ float  g_att[Bn*Sn*HDn];
__device__ int    g_idx[Bn];
__device__ float  g_v[Bn*CHn*Hn*Wn];          // 64 MB activation
__device__ float2 g_X[Bn*KXn*16*CHn];         // fwd coeffs [b][kx][ky][c]
__device__ float2 g_Y[Bn*CHn*KXn*16];         // mixed [b][o][kx][ky]
__device__ float2 g_Z[Bn*CHn*Hn*16];          // inv h-DFT [b][o][h][ky]

__device__ __forceinline__ float gelu_tanh(float x) {
    float x3 = x*x*x;
    float z  = 0.7978845608028654f*(x + 0.044715f*x3);
    float t  = 1.0f - 2.0f/(__expf(2.0f*z) + 1.0f);
    return 0.5f*x*(1.0f + t);
}

// ========================= ROUTER =========================

__global__ void k_encode(const float* __restrict__ x,
                         const float* __restrict__ w,
                         const float* __restrict__ b) {
    int i = blockIdx.x*blockDim.x + threadIdx.x;
    const int tot = Bn*Sn*HDn;
    for (; i < tot; i += gridDim.x*blockDim.x) {
        int d = i & 63;
        int s = (i >> 6) & 127;
        int bb = i >> 13;
        g_h[i] = x[bb*(Hn*Wn) + s]*w[d] + b[d];
    }
}

// fused qkv + flash attention; block = (b, head), 128 threads
__global__ __launch_bounds__(128) void k_attn_qkv(const float* __restrict__ qw,
                                                  const float* __restrict__ qb, int l) {
    __shared__ float hs[128*64];
    __shared__ float kvs[4096];
    int b = blockIdx.x >> 2, hd = blockIdx.x & 3;
    int i = threadIdx.x;
    {
        const float4* src = (const float4*)(g_h + b*8192);
        float4* dst = (float4*)hs;
        for (int p = i; p < 2048; p += 128) dst[p] = src[p];
    }
    float* Ws = kvs;
    {
        const float* W = qw + l*64*192;
        for (int p = i; p < 3072; p += 128) {
            int d = p/48, c = p - d*48;
            int gc = hd*16 + (c & 15) + (c >> 4)*64;
            Ws[p] = W[d*192 + gc];
        }
    }
    __syncthreads();

    float q[16], kk[16], vv[16];
    {
        const float* qbl = qb + l*192 + hd*16;
        #pragma unroll
        for (int j = 0; j < 16; j++) { q[j]=qbl[j]; kk[j]=qbl[64+j]; vv[j]=qbl[128+j]; }
        for (int d = 0; d < 64; d++) {
            float hv = hs[i*64 + d];
            const float4* wr = (const float4*)(Ws + d*48);
            #pragma unroll
            for (int jj = 0; jj < 4; jj++) {
                float4 wq = wr[jj], wk = wr[4+jj], wv = wr[8+jj];
                q [jj*4+0] += hv*wq.x; q [jj*4+1] += hv*wq.y; q [jj*4+2] += hv*wq.z; q [jj*4+3] += hv*wq.w;
                kk[jj*4+0] += hv*wk.x; kk[jj*4+1] += hv*wk.y; kk[jj*4+2] += hv*wk.z; kk[jj*4+3] += hv*wk.w;
                vv[jj*4+0] += hv*wv.x; vv[jj*4+1] += hv*wv.y; vv[jj*4+2] += hv*wv.z; vv[jj*4+3] += hv*wv.w;
            }
        }
    }
    __syncthreads();
    float* ks = kvs;
    float* vs = kvs + 2048;
    #pragma unroll
    for (int j = 0; j < 16; j++) { ks[i*16+j] = kk[j]; vs[i*16+j] = vv[j]; }
    __syncthreads();

    float m = -1e30f, ssum = 0.f;
    float out[16];
    #pragma unroll
    for (int d = 0; d < 16; d++) out[d] = 0.f;
    for (int j = 0; j < 128; j++) {
        float s = 0.f;
        #pragma unroll
        for (int d = 0; d < 16; d++) s += q[d]*ks[j*16+d];
        s *= 0.25f;
        float mn = fmaxf(m, s);
        float corr = __expf(m - mn);
        float wj = __expf(s - mn);
        ssum = ssum*corr + wj;
        #pragma unroll
        for (int d = 0; d < 16; d++) out[d] = out[d]*corr + wj*vs[j*16+d];
        m = mn;
    }
    float inv = 1.0f/ssum;
    float* ob = g_att + (b*128+i)*64 + hd*16;
    #pragma unroll
    for (int d = 0; d < 16; d++) ob[d] = out[d]*inv;
}

// fused: h = LN1(h + att@ao + ab); h = LN2(h + relu(h@W1+b1)@W2 + b2)
__global__ __launch_bounds__(256) void k_plf(
        const float* __restrict__ aw, const float* __restrict__ ab,
        const float* __restrict__ lns, const float* __restrict__ lnb,
        const float* __restrict__ w1, const float* __restrict__ b1,
        const float* __restrict__ w2, const float* __restrict__ b2,
        const float* __restrict__ ln2s, const float* __restrict__ ln2b, int l) {
    __shared__ float as_[1024], ts[1024], hs[1024];
    __shared__ float hid[4096];
    __shared__ float red[4096];
    int row0 = blockIdx.x*16;
    int tid = threadIdx.x;
    int warp = tid >> 5, lane = tid & 31;

    for (int p = tid; p < 1024; p += 256) as_[p] = g_att[row0*64 + p];
    __syncthreads();
    const float* wl = aw + l*64*64;
    for (int p = tid; p < 1024; p += 256) {
        int r = p >> 6, d = p & 63;
        float acc = g_h[(row0+r)*64 + d] + ab[l*64 + d];
        #pragma unroll
        for (int e = 0; e < 64; e++) acc += as_[r*64+e]*wl[e*64+d];
        ts[p] = acc;
    }
    __syncthreads();
    // LN1 -> hs
    {
        const float* s_ = lns + l*64; const float* b_ = lnb + l*64;
        #pragma unroll
        for (int rr = 0; rr < 2; rr++) {
            int r = warp*2 + rr;
            float a = ts[r*64+lane], bv = ts[r*64+32+lane];
            float s = a + bv, qq = a*a + bv*bv;
            #pragma unroll
            for (int off = 16; off > 0; off >>= 1) {
                s  += __shfl_xor_sync(0xffffffff, s,  off);
                qq += __shfl_xor_sync(0xffffffff, qq, off);
            }
            float mu = s*(1.0f/64.0f);
            float var = qq*(1.0f/64.0f) - mu*mu;
            float rs = rsqrtf(var + 1e-5f);
            hs[r*64+lane]    = (a  - mu)*rs*s_[lane]    + b_[lane];
            hs[r*64+32+lane] = (bv - mu)*rs*s_[32+lane] + b_[32+lane];
        }
    }
    __syncthreads();
    // FF1 register-tiled
    {
        const float* W1 = w1 + l*16384;
        int rq = tid >> 6, jg = tid & 63;
        int j0 = jg*4;
        float4 bv = *(const float4*)(b1 + l*256 + j0);
        float acc[4][4];
        #pragma unroll
        for (int rr = 0; rr < 4; rr++) {
            acc[rr][0]=bv.x; acc[rr][1]=bv.y; acc[rr][2]=bv.z; acc[rr][3]=bv.w;
        }
        #pragma unroll 4
        for (int d = 0; d < 64; d++) {
            float4 wv = *(const float4*)(W1 + d*256 + j0);
            #pragma unroll
            for (int rr = 0; rr < 4; rr++) {
                float hv = hs[(rq*4+rr)*64 + d];
                acc[rr][0] += hv*wv.x; acc[rr][1] += hv*wv.y;
                acc[rr][2] += hv*wv.z; acc[rr][3] += hv*wv.w;
            }
        }
        #pragma unroll
        for (int rr = 0; rr < 4; rr++)
            #pragma unroll
            for (int jj = 0; jj < 4; jj++)
                hid[(rq*4+rr)*256 + j0 + jj] = fmaxf(acc[rr][jj], 0.0f);
    }
    __syncthreads();
    // FF2, 4-way j split
    {
        const float* W2 = w2 + l*16384;
        int dq = tid & 15, rq = (tid >> 4) & 3, js = tid >> 6;
        int d0 = dq*4, r0 = rq*4, j0 = js*64;
        float acc[4][4];
        #pragma unroll
        for (int rr = 0; rr < 4; rr++)
            #pragma unroll
            for (int dd = 0; dd < 4; dd++) acc[rr][dd] = 0.f;
        #pragma unroll 4
        for (int jj = 0; jj < 64; jj++) {
            int j = j0 + jj;
            float4 wv = *(const float4*)(W2 + j*64 + d0);
            #pragma unroll
            for (int rr = 0; rr < 4; rr++) {
                float hv = hid[(r0+rr)*256 + j];
                acc[rr][0] += hv*wv.x; acc[rr][1] += hv*wv.y;
                acc[rr][2] += hv*wv.z; acc[rr][3] += hv*wv.w;
            }
        }
        #pragma unroll
        for (int rr = 0; rr < 4; rr++)
            #pragma unroll
            for (int dd = 0; dd < 4; dd++)
                red[js*1024 + (r0+rr)*64 + d0+dd] = acc[rr][dd];
    }
    __syncthreads();
    for (int p = tid; p < 1024; p += 256) {
        int d = p & 63;
        ts[p] = red[p] + red[1024+p] + red[2048+p] + red[3072+p] + hs[p] + b2[l*64+d];
    }
    __syncthreads();
    // LN2 -> g_h
    {
        const float* s_ = ln2s + l*64; const float* b_ = ln2b + l*64;
        #pragma unroll
        for (int rr = 0; rr < 2; rr++) {
            int r = warp*2 + rr;
            float a = ts[r*64+lane], bv = ts[r*64+32+lane];
            float s = a + bv, qq = a*a + bv*bv;
            #pragma unroll
            for (int off = 16; off > 0; off >>= 1) {
                s  += __shfl_xor_sync(0xffffffff, s,  off);
                qq += __shfl_xor_sync(0xffffffff, qq, off);
            }
            float mu = s*(1.0f/64.0f);
            float var = qq*(1.0f/64.0f) - mu*mu;
            float rs = rsqrtf(var + 1e-5f);
            g_h[(row0+r)*64+lane]    = (a  - mu)*rs*s_[lane]    + b_[lane];
            g_h[(row0+r)*64+32+lane] = (bv - mu)*rs*s_[32+lane] + b_[32+lane];
        }
    }
}

__global__ void k_head(const float* __restrict__ fcw, const float* __restrict__ fcb) {
    __shared__ float feats[Bn*64];
    for (int p = threadIdx.x; p < Bn*64; p += blockDim.x) {
        int b = p >> 6, d = p & 63;
        float acc = 0.f;
        for (int s = 0; s < 128; s++) acc += g_h[(b*128+s)*64 + d];
        feats[p] = acc*(1.0f/128.0f);
    }
    __syncthreads();
    if (threadIdx.x < Bn) {
        int b = threadIdx.x;
        float best = -1e30f; int bi = 0;
        for (int e = 0; e < En; e++) {
            float acc = fcb[e];
            for (int d = 0; d < 64; d++) acc += feats[b*64+d]*fcw[d*En+e];
            if (acc > best) { best = acc; bi = e; }
        }
        g_idx[b] = bi;
    }
}

// ========================= FNO =========================

__global__ __launch_bounds__(256) void k_lift(const float* __restrict__ x,
                                              const float* __restrict__ lw,
                                              const float* __restrict__ lb) {
    __shared__ float xr[128];
    __shared__ float ws[32], bs[32];
    int bb = blockIdx.x >> 7, h = blockIdx.x & 127;
    int e = g_idx[bb];
    if (threadIdx.x < 128) xr[threadIdx.x] = x[bb*16384 + h*128 + threadIdx.x];
    if (threadIdx.x < 32) { ws[threadIdx.x] = lw[e*32+threadIdx.x]; bs[threadIdx.x] = lb[e*32+threadIdx.x]; }
    __syncthreads();
    for (int p = threadIdx.x; p < 4096; p += 256) {
        int d = p >> 7, w = p & 127;
        g_v[((bb*32+d)*128 + h)*128 + w] = xr[w]*ws[d] + bs[d];
    }
}

// fused 2D forward partial DFT per (b,c), with w-mirror and +/-kx symmetry.
__global__ __launch_bounds__(256) void k_dft2() {
    extern __shared__ float sm[];
    float*  vs = sm;                      // 8448
    float2* Az = (float2*)(sm + 8448);    // 2048 cplx
    float*  Tc = sm + 8448 + 4096;        // 1024
    float*  Ts = Tc + 1024;               // 1024
    float*  ct = Ts + 1024;               // 128
    float*  st = ct + 128;                // 128
    int bb = blockIdx.x >> 5, c = blockIdx.x & 31;
    int tid = threadIdx.x;
    if (tid < 128) {
        float ang = 6.283185307179586f*(float)tid/128.0f;
        ct[tid] = cosf(ang); st[tid] = sinf(ang);
    }
    for (int p = tid; p < 1024; p += 256) {
        int w = p >> 4, k = p & 15;
        int t = (w*k) & 127;
        float ang = 0.0490873852123405f*(float)t;
        Tc[p] = cosf(ang); Ts[p] = sinf(ang);
    }
    const float* vg = g_v + (bb*32 + c)*16384;
    int hl = tid >> 2, kq = tid & 3, ky0 = kq*4;
    for (int half = 0; half < 2; half++) {
        __syncthreads();
        for (int p = tid; p < 2048; p += 256) {
            int r = p >> 5, q = p & 31;
            ((float4*)(vs + r*132))[q] = ((const float4*)(vg + (half*64 + r)*128))[q];
        }
        __syncthreads();
        const float* vr = vs + hl*132;
        float v0 = vr[0], v64 = vr[64];
        float re[4], im[4];
        #pragma unroll
        for (int j = 0; j < 4; j++) {
            re[j] = v0 + (((ky0+j) & 1) ? -v64 : v64);
            im[j] = 0.f;
        }
        #pragma unroll 7
        for (int w = 1; w < 64; w++) {
            float a = vr[w], b = vr[128-w];
            float s_ = a + b, d_ = a - b;
            float4 c4 = *(const float4*)(Tc + w*16 + ky0);
            float4 s4 = *(const float4*)(Ts + w*16 + ky0);
            re[0] += s_*c4.x; im[0] -= d_*s4.x;
            re[1] += s_*c4.y; im[1] -= d_*s4.y;
            re[2] += s_*c4.z; im[2] -= d_*s4.z;
            re[3] += s_*c4.w; im[3] -= d_*s4.w;
        }
        #pragma unroll
        for (int j = 0; j < 4; j++)
            Az[(half*64 + hl)*16 + ky0 + j] = make_float2(re[j], im[j]);
    }
    __syncthreads();
    // stage 2: h-DFT with +/-kx pairing
    int g = tid >> 4, ky = tid & 15;
    if (g == 0) {
        float rex=0.f, imx=0.f, re16=0.f, im16=0.f;
        int t = 0;
        for (int h = 0; h < 128; h++) {
            float2 a = Az[h*16 + ky];
            rex += a.x; imx += a.y;
            float cc = ct[t], ss = st[t];
            re16 += a.x*cc - a.y*ss;   // kx = -16
            im16 += a.y*cc + a.x*ss;
            t = (t + 16) & 127;
        }
        g_X[((bb*32 + 0 )*16 + ky)*32 + c] = make_float2(rex,  imx);
        g_X[((bb*32 + 16)*16 + ky)*32 + c] = make_float2(re16, im16);
    } else {
        float u=0.f, v=0.f, pp=0.f, qq=0.f;
        int t = 0;
        for (int h = 0; h < 128; h++) {
            float2 a = Az[h*16 + ky];
            float cc = ct[t], ss = st[t];
            u  += a.x*cc; qq += a.x*ss;
            pp += a.y*cc; v  += a.y*ss;
            t = (t + g) & 127;
        }
        g_X[((bb*32 + g     )*16 + ky)*32 + c] = make_float2(u+v, pp-qq);
        g_X[((bb*32 + (32-g))*16 + ky)*32 + c] = make_float2(u-v, pp+qq);
    }
}

// spectral mix (unchanged)
__global__ __launch_bounds__(256) void k_mix(const float* __restrict__ wr,
                                             const float* __restrict__ wi, int l) {
    __shared__ float2 Xs[16*32];
    int bb = blockIdx.x >> 5, kxi = blockIdx.x & 31;
    int e = g_idx[bb];
    int r   = (kxi < 16) ? 0 : 1;
    int kxp = (kxi < 16) ? kxi : kxi - 16;
    const float2* src = g_X + ((bb*32 + kxi)*16)*32;
    for (int p = threadIdx.x; p < 512; p += 256) Xs[p] = src[p];
    __syncthreads();
    int base = ((e*4 + l)*2 + r)*(32*32*256);
    const float* wrb = wr + base + kxp*16;
    const float* wib = wi + base + kxp*16;
    for (int p = threadIdx.x; p < 512; p += 256) {
        int o = p >> 4, ky = p & 15;
        float re = 0.f, im = 0.f;
        #pragma unroll 8
        for (int i = 0; i < 32; i++) {
            float2 xv = Xs[ky*32 + i];
            float wre = wrb[i*8192 + o*256 + ky];
            float wim = wib[i*8192 + o*256 + ky];
            re += xv.x*wre - xv.y*wim;
            im += xv.x*wim + xv.y*wre;
        }
        g_Y[((bb*32 + o)*32 + kxi)*16 + ky] = make_float2(re, im);
    }
}

// inverse h-DFT with S/D symmetry: 17 paired terms instead of 32
__global__ __launch_bounds__(256) void k_idft2() {
    __shared__ __align__(16) float2 Ssm[17*16];
    __shared__ __align__(16) float2 Dsm[17*16];
    __shared__ float ct[128], st[128];
    int bb = blockIdx.x >> 5, o = blockIdx.x & 31;
    int tid = threadIdx.x;
    if (tid < 128) {
        float ang = 6.283185307179586f*(float)tid/128.0f;
        ct[tid] = cosf(ang); st[tid] = sinf(ang);
    }
    const float2* Yb = g_Y + ((bb*32 + o)*32)*16;  // [kxi][ky]
    for (int p = tid; p < 272; p += 256) {         // FIX: loop, 272 > blockDim
        int g = p >> 4, ky = p & 15;
        float2 S, D;
        if (g == 0)      { S = Yb[ky]; D = make_float2(0.f, 0.f); }
        else if (g < 16) {
            float2 a = Yb[g*16 + ky], b = Yb[(32-g)*16 + ky];
            S = make_float2(a.x+b.x, a.y+b.y);
            D = make_float2(a.x-b.x, a.y-b.y);
        } else {
            float2 a = Yb[16*16 + ky];
            S = a; D = make_float2(-a.x, -a.y);
        }
        Ssm[p] = S; Dsm[p] = D;
    }
    __syncthreads();
    int h = tid >> 1, ky0 = (tid & 1)*8;
    float zr[8], zi[8];
    #pragma unroll
    for (int j = 0; j < 8; j++) { zr[j]=0.f; zi[j]=0.f; }
    #pragma unroll
    for (int g = 0; g <= 16; g++) {
        int t = (g*h) & 127;
        float cc = ct[t], ss = st[t];
        const float4* Sp = (const float4*)(Ssm + g*16 + ky0);
        const float4* Dp = (const float4*)(Dsm + g*16 + ky0);
        #pragma unroll
        for (int jj = 0; jj < 4; jj++) {
            float4 Sv = Sp[jj], Dv = Dp[jj];
            zr[jj*2]   += cc*Sv.x - ss*Dv.y;
            zi[jj*2]   += cc*Sv.y + ss*Dv.x;
            zr[jj*2+1] += cc*Sv.z - ss*Dv.w;
            zi[jj*2+1] += cc*Sv.w + ss*Dv.z;
        }
    }
    float2* dst = g_Z + ((bb*32 + o)*128 + h)*16 + ky0;
    #pragma unroll
    for (int j = 0; j < 8; j++) dst[j] = make_float2(zr[j], zi[j]);
}

// combine as one K=64 GEMM: rows 0..30 irfft-w twiddles, 31..62 v (skip), 63 bias
__global__ __launch_bounds__(128) void k_comb64(const float* __restrict__ sw,
                                                const float* __restrict__ sb,
                                                int l, int last) {
    __shared__ __align__(16) float Bk[64*128];
    __shared__ __align__(16) float Ak[64*32];
    int bb = blockIdx.x >> 7, h = blockIdx.x & 127;
    int e = g_idx[bb];
    int tid = threadIdx.x;

    for (int p = tid; p < 31*128; p += 128) {
        int k = p >> 7, w = p & 127;
        float val;
        if (k == 0) val = 1.0f;
        else if (k < 16) { int t = (k*w) & 127;      val = __cosf(0.0490873852123405f*(float)t); }
        else             { int t = ((k-15)*w) & 127; val = __sinf(0.0490873852123405f*(float)t); }
        Bk[p] = val;
    }
    Bk[63*128 + tid] = 1.0f;
    for (int p = tid; p < 1024; p += 128) {
        int i = p >> 5, q = p & 31;
        ((float4*)(Bk + (31+i)*128))[q] = ((const float4*)(g_v + ((bb*32+i)*128+h)*128))[q];
    }
    for (int p = tid; p < 512; p += 128) {
        int o = p & 31, ky = p >> 5;
        float2 z = g_Z[((bb*32+o)*128+h)*16 + ky];
        const float s2 = 2.0f/16384.0f;
        if (ky == 0) Ak[o] = z.x*(1.0f/16384.0f);
        else { Ak[ky*32+o] = z.x*s2; Ak[(15+ky)*32+o] = -z.y*s2; }
    }
    for (int p = tid; p < 1024; p += 128)
        Ak[(31 + (p>>5))*32 + (p & 31)] = sw[(e*4+l)*1024 + p];
    if (tid < 32) Ak[63*32 + tid] = sb[(e*4+l)*32 + tid];
    __syncthreads();

    int wg = tid & 31, og = tid >> 5;   // w = wg*4.., o = og*8..
    float acc[8][4];
    #pragma unroll
    for (int i = 0; i < 8; i++)
        #pragma unroll
        for (int j = 0; j < 4; j++) acc[i][j] = 0.f;
    #pragma unroll 8
    for (int k = 0; k < 64; k++) {
        float4 bv = ((const float4*)(Bk + k*128))[wg];
        float4 a0 = ((const float4*)(Ak + k*32))[og*2];
        float4 a1 = ((const float4*)(Ak + k*32))[og*2+1];
        acc[0][0]+=a0.x*bv.x; acc[0][1]+=a0.x*bv.y; acc[0][2]+=a0.x*bv.z; acc[0][3]+=a0.x*bv.w;
        acc[1][0]+=a0.y*bv.x; acc[1][1]+=a0.y*bv.y; acc[1][2]+=a0.y*bv.z; acc[1][3]+=a0.y*bv.w;
        acc[2][0]+=a0.z*bv.x; acc[2][1]+=a0.z*bv.y; acc[2][2]+=a0.z*bv.z; acc[2][3]+=a0.z*bv.w;
        acc[3][0]+=a0.w*bv.x; acc[3][1]+=a0.w*bv.y; acc[3][2]+=a0.w*bv.z; acc[3][3]+=a0.w*bv.w;
        acc[4][0]+=a1.x*bv.x; acc[4][1]+=a1.x*bv.y; acc[4][2]+=a1.x*bv.z; acc[4][3]+=a1.x*bv.w;
        acc[5][0]+=a1.y*bv.x; acc[5][1]+=a1.y*bv.y; acc[5][2]+=a1.y*bv.z; acc[5][3]+=a1.y*bv.w;
        acc[6][0]+=a1.z*bv.x; acc[6][1]+=a1.z*bv.y; acc[6][2]+=a1.z*bv.z; acc[6][3]+=a1.z*bv.w;
        acc[7][0]+=a1.w*bv.x; acc[7][1]+=a1.w*bv.y; acc[7][2]+=a1.w*bv.z; acc[7][3]+=a1.w*bv.w;
    }
    #pragma unroll
    for (int i = 0; i < 8; i++) {
        int o = og*8 + i;
        float v0 = acc[i][0], v1 = acc[i][1], v2 = acc[i][2], v3 = acc[i][3];
        if (!last) { v0 = gelu_tanh(v0); v1 = gelu_tanh(v1); v2 = gelu_tanh(v2); v3 = gelu_tanh(v3); }
        ((float4*)(g_v + ((bb*32+o)*128+h)*128))[wg] = make_float4(v0, v1, v2, v3);
    }
}

// projection (unchanged)
__global__ __launch_bounds__(256, 2) void k_proj2(
        const float* __restrict__ p1w, const float* __restrict__ p1b,
        const float* __restrict__ p2w, const float* __restrict__ p2b,
        float* __restrict__ out) {
    __shared__ float vs [32*128];
    __shared__ float w1p[32*128];
    __shared__ float red[16*128];
    __shared__ float b1s[128], p2s[128];
    int bb = blockIdx.x >> 7, h = blockIdx.x & 127;
    int e = g_idx[bb];
    int tid = threadIdx.x;
    #pragma unroll
    for (int j = 0; j < 4; j++) {
        int p = tid + 256*j;
        int i = p >> 5, q = p & 31;
        ((float4*)(vs + i*128))[q] = ((const float4*)(g_v + ((bb*32+i)*128+h)*128))[q];
    }
    for (int p = tid; p < 4096; p += 256) {
        float val = p1w[e*4096 + p];
        int c = p >> 7, pch = p & 127;
        w1p[c*128 + (pch & 15)*8 + (pch >> 4)] = val;
    }
    if (tid < 128) {
        b1s[tid] = p1b[e*128 + tid];
        p2s[tid] = p2w[e*128 + tid];
    }
    __syncthreads();

    int wg = tid & 15, pg = tid >> 4;
    int w0 = wg*8;
    float acc[8][8];
    #pragma unroll
    for (int i = 0; i < 8; i++)
        #pragma unroll
        for (int j = 0; j < 8; j++) acc[i][j] = 0.f;
    #pragma unroll 2
    for (int c = 0; c < 32; c++) {
        float4 v0 = ((const float4*)(vs + c*128 + w0))[0];
        float4 v1 = ((const float4*)(vs + c*128 + w0))[1];
        float4 u0 = ((const float4*)(w1p + c*128 + pg*8))[0];
        float4 u1 = ((const float4*)(w1p + c*128 + pg*8))[1];
        float vv[8] = {v0.x,v0.y,v0.z,v0.w,v1.x,v1.y,v1.z,v1.w};
        float uu[8] = {u0.x,u0.y,u0.z,u0.w,u1.x,u1.y,u1.z,u1.w};
        #pragma unroll
        for (int i = 0; i < 8; i++)
            #pragma unroll
            for (int j = 0; j < 8; j++)
                acc[i][j] += uu[i]*vv[j];
    }
    float part[8];
    #pragma unroll
    for (int j = 0; j < 8; j++) part[j] = 0.f;
    #pragma unroll
    for (int i = 0; i < 8; i++) {
        int pch = pg + 16*i;
        float bias = b1s[pch], p2v = p2s[pch];
        #pragma unroll
        for (int j = 0; j < 8; j++)
            part[j] += gelu_tanh(acc[i][j] + bias)*p2v;
    }
    #pragma unroll
    for (int j = 0; j < 8; j++) red[pg*128 + w0 + j] = part[j];
    __syncthreads();
    if (tid < 128) {
        int w = tid;
        float o = p2b[e];
        #pragma unroll
        for (int pg2 = 0; pg2 < 16; pg2++) o += red[pg2*128 + w];
        out[bb*16384 + h*128 + w] = o;
    }
}

// ========================= launch =========================
extern "C" void kernel_launch(void* const* d_in, const int* in_sizes, int n_in,
                              void* d_out, int out_size) {
    const float* x        = (const float*)d_in[0];
    const float* enc_in_w = (const float*)d_in[1];
    const float* enc_in_b = (const float*)d_in[2];
    const float* qkv_w    = (const float*)d_in[3];
    const float* qkv_b    = (const float*)d_in[4];
    const float* ao_w     = (const float*)d_in[5];
    const float* ao_b     = (const float*)d_in[6];
    const float* ln1_s    = (const float*)d_in[7];
    const float* ln1_b    = (const float*)d_in[8];
    const float* ff1_w    = (const float*)d_in[9];
    const float* ff1_b    = (const float*)d_in[10];
    const float* ff2_w    = (const float*)d_in[11];
    const float* ff2_b    = (const float*)d_in[12];
    const float* ln2_s    = (const float*)d_in[13];
    const float* ln2_b    = (const float*)d_in[14];
    const float* fc_w     = (const float*)d_in[15];
    const float* fc_b     = (const float*)d_in[16];
    const float* lift_w   = (const float*)d_in[17];
    const float* lift_b   = (const float*)d_in[18];
    const float* spec_wr  = (const float*)d_in[19];
    const float* spec_wi  = (const float*)d_in[20];
    const float* skip_w   = (const float*)d_in[21];
    const float* skip_b   = (const float*)d_in[22];
    const float* p1_w     = (const float*)d_in[23];
    const float* p1_b     = (const float*)d_in[24];
    const float* p2_w     = (const float*)d_in[25];
    const float* p2_b     = (const float*)d_in[26];

    cudaFuncSetAttribute(k_dft2, cudaFuncAttributeMaxDynamicSharedMemorySize, 59392);

    // ---- router ----
    k_encode<<<256, 256>>>(x, enc_in_w, enc_in_b);
    for (int l = 0; l < NENCn; l++) {
        k_attn_qkv<<<Bn*NHn, 128>>>(qkv_w, qkv_b, l);
        k_plf<<<(Bn*Sn)/16, 256>>>(ao_w, ao_b, ln1_s, ln1_b,
                                   ff1_w, ff1_b, ff2_w, ff2_b, ln2_s, ln2_b, l);
    }
    k_head<<<1, 1024>>>(fc_w, fc_b);

    // ---- FNO ----
    k_lift<<<Bn*Hn, 256>>>(x, lift_w, lift_b);
    for (int l = 0; l < NLn; l++) {
        k_dft2<<<Bn*CHn, 256, 59392>>>();
        k_mix<<<Bn*KXn, 256>>>(spec_wr, spec_wi, l);
        k_idft2<<<Bn*CHn, 256>>>();
        k_comb64<<<Bn*Hn, 128>>>(skip_w, skip_b, l, (l == NLn-1) ? 1 : 0);
    }
    k_proj2<<<Bn*Hn, 256>>>(p1_w, p1_b, p2_w, p2_b, (float*)d_out);
}

// round 9
// speedup vs baseline: 2.4844x; 1.1112x over previous
#include <cuda_runtime.h>
#include <math.h>

// ---------------- problem constants ----------------
#define Bn   32
#define Sn   128
#define HDn  64
#define NHn  4
#define NENCn 2
#define En   8
#define NLn  4
#define CHn  32
#define Hn   128
#define Wn   128
#define PCHn 128
#define KXn  32

// ---------------- device scratch ----------------
__device__ float  g_h  [Bn*Sn*HDn];
__device__ float  g_att[Bn*Sn*HDn];
__device__ int    g_idx[Bn];
__device__ float  g_v[Bn*CHn*Hn*Wn];          // 64 MB activation
__device__ float2 g_X[Bn*KXn*16*CHn];         // fwd coeffs [b][kx][ky][c]
__device__ float2 g_Y[Bn*CHn*KXn*16];         // mixed [b][o][kx][ky]
__device__ float2 g_Z[Bn*CHn*Hn*16];          // inv h-DFT [b][o][h][ky]
__device__ float  g_Tw[32*128];               // irfft-w twiddles (31 rows) + ones row

__device__ __forceinline__ float gelu_tanh(float x) {
    float x3 = x*x*x;
    float z  = 0.7978845608028654f*(x + 0.044715f*x3);
    float t  = 1.0f - 2.0f/(__expf(2.0f*z) + 1.0f);
    return 0.5f*x*(1.0f + t);
}

// ========================= init: twiddle table =========================
// rows 0..30: [1, cos(k w), sin((k-15) w)], row 31: ones
__global__ void k_tw() {
    int k = blockIdx.x, w = threadIdx.x;
    float val;
    if (k == 0)       val = 1.0f;
    else if (k < 16)  { int t = (k*w) & 127;      val = cosf(0.0490873852123405f*(float)t); }
    else if (k < 31)  { int t = ((k-15)*w) & 127; val = sinf(0.0490873852123405f*(float)t); }
    else              val = 1.0f;
    g_Tw[k*128 + w] = val;
}

// ========================= ROUTER =========================

__global__ void k_encode(const float* __restrict__ x,
                         const float* __restrict__ w,
                         const float* __restrict__ b) {
    int i = blockIdx.x*blockDim.x + threadIdx.x;
    const int tot = Bn*Sn*HDn;
    for (; i < tot; i += gridDim.x*blockDim.x) {
        int d = i & 63;
        int s = (i >> 6) & 127;
        int bb = i >> 13;
        g_h[i] = x[bb*(Hn*Wn) + s]*w[d] + b[d];
    }
}

// fused qkv + flash attention, 2-way split softmax; block = (b, head), 256 threads
__global__ __launch_bounds__(256) void k_attn_qkv(const float* __restrict__ qw,
                                                  const float* __restrict__ qb, int l) {
    __shared__ float buf[11264];   // 44 KB
    int b = blockIdx.x >> 2, hd = blockIdx.x & 3;
    int tid = threadIdx.x;
    int i = tid & 127, half = tid >> 7;

    float* hs = buf;            // [128][64] (phase A)
    float* Ws = buf + 8192;     // [64][48]  (phase A)
    for (int p = tid; p < 2048; p += 256)
        ((float4*)hs)[p] = ((const float4*)(g_h + b*8192))[p];
    {
        const float* W = qw + l*64*192;
        for (int p = tid; p < 3072; p += 256) {
            int d = p/48, c = p - d*48;
            int gc = hd*16 + (c & 15) + (c >> 4)*64;
            Ws[p] = W[d*192 + gc];
        }
    }
    __syncthreads();

    // each (i, half): q always; half0 also k, half1 also v
    float q[16], kv[16];
    {
        const float* qbl = qb + l*192 + hd*16;
        int kvoff = half ? 128 : 64;
        #pragma unroll
        for (int j = 0; j < 16; j++) { q[j] = qbl[j]; kv[j] = qbl[kvoff + j]; }
        int woff = half ? 8 : 4;
        for (int d = 0; d < 64; d++) {
            float hv = hs[i*64 + d];
            const float4* wr = (const float4*)(Ws + d*48);
            #pragma unroll
            for (int jj = 0; jj < 4; jj++) {
                float4 wq = wr[jj], wk = wr[woff + jj];
                q [jj*4+0] += hv*wq.x; q [jj*4+1] += hv*wq.y; q [jj*4+2] += hv*wq.z; q [jj*4+3] += hv*wq.w;
                kv[jj*4+0] += hv*wk.x; kv[jj*4+1] += hv*wk.y; kv[jj*4+2] += hv*wk.z; kv[jj*4+3] += hv*wk.w;
            }
        }
    }
    __syncthreads();   // done reading hs/Ws; reuse buf

    float* ks   = buf;          // [128][16]
    float* vs   = buf + 2048;   // [128][16]
    float* mArr = buf + 4096;   // [256]
    float* sArr = buf + 4352;   // [256]
    float* oArr = buf + 4608;   // [256][16]
    {
        float* dst = (half ? vs : ks) + i*16;
        #pragma unroll
        for (int j = 0; j < 16; j++) dst[j] = kv[j];
    }
    __syncthreads();

    // online softmax over this half's 64 keys, 2-j unrolled
    int j0 = half*64;
    float m = -1e30f, ssum = 0.f;
    float out[16];
    #pragma unroll
    for (int d = 0; d < 16; d++) out[d] = 0.f;
    for (int jj = 0; jj < 64; jj += 2) {
        int j = j0 + jj;
        const float* k1 = ks + j*16;
        const float* k2 = k1 + 16;
        float s1 = 0.f, s2 = 0.f;
        #pragma unroll
        for (int d = 0; d < 16; d++) { s1 += q[d]*k1[d]; s2 += q[d]*k2[d]; }
        s1 *= 0.25f; s2 *= 0.25f;
        float mn = fmaxf(m, fmaxf(s1, s2));
        float corr = __expf(m - mn);
        float w1 = __expf(s1 - mn), w2 = __expf(s2 - mn);
        ssum = ssum*corr + w1 + w2;
        const float* v1 = vs + j*16;
        const float* v2 = v1 + 16;
        #pragma unroll
        for (int d = 0; d < 16; d++) out[d] = out[d]*corr + w1*v1[d] + w2*v2[d];
        m = mn;
    }
    mArr[tid] = m; sArr[tid] = ssum;
    {
        float* od = oArr + tid*16;
        #pragma unroll
        for (int d = 0; d < 16; d++) od[d] = out[d];
    }
    __syncthreads();

    if (half == 0) {
        float m1 = mArr[128 + i], s1v = sArr[128 + i];
        float M  = fmaxf(m, m1);
        float c0 = __expf(m - M), c1 = __expf(m1 - M);
        float inv = 1.0f/(ssum*c0 + s1v*c1);
        const float* o1 = oArr + (128 + i)*16;
        float* ob = g_att + (b*128 + i)*64 + hd*16;
        #pragma unroll
        for (int d = 0; d < 16; d++) ob[d] = (out[d]*c0 + o1[d]*c1)*inv;
    }
}

// fused: h = LN1(h + att@ao + ab); h = LN2(h + relu(h@W1+b1)@W2 + b2)
__global__ __launch_bounds__(256) void k_plf(
        const float* __restrict__ aw, const float* __restrict__ ab,
        const float* __restrict__ lns, const float* __restrict__ lnb,
        const float* __restrict__ w1, const float* __restrict__ b1,
        const float* __restrict__ w2, const float* __restrict__ b2,
        const float* __restrict__ ln2s, const float* __restrict__ ln2b, int l) {
    __shared__ float as_[1024], ts[1024], hs[1024];
    __shared__ float hid[4096];
    __shared__ float red[4096];
    int row0 = blockIdx.x*16;
    int tid = threadIdx.x;
    int warp = tid >> 5, lane = tid & 31;

    for (int p = tid; p < 1024; p += 256) as_[p] = g_att[row0*64 + p];
    __syncthreads();
    const float* wl = aw + l*64*64;
    for (int p = tid; p < 1024; p += 256) {
        int r = p >> 6, d = p & 63;
        float acc = g_h[(row0+r)*64 + d] + ab[l*64 + d];
        #pragma unroll
        for (int e = 0; e < 64; e++) acc += as_[r*64+e]*wl[e*64+d];
        ts[p] = acc;
    }
    __syncthreads();
    // LN1 -> hs
    {
        const float* s_ = lns + l*64; const float* b_ = lnb + l*64;
        #pragma unroll
        for (int rr = 0; rr < 2; rr++) {
            int r = warp*2 + rr;
            float a = ts[r*64+lane], bv = ts[r*64+32+lane];
            float s = a + bv, qq = a*a + bv*bv;
            #pragma unroll
            for (int off = 16; off > 0; off >>= 1) {
                s  += __shfl_xor_sync(0xffffffff, s,  off);
                qq += __shfl_xor_sync(0xffffffff, qq, off);
            }
            float mu = s*(1.0f/64.0f);
            float var = qq*(1.0f/64.0f) - mu*mu;
            float rs = rsqrtf(var + 1e-5f);
            hs[r*64+lane]    = (a  - mu)*rs*s_[lane]    + b_[lane];
            hs[r*64+32+lane] = (bv - mu)*rs*s_[32+lane] + b_[32+lane];
        }
    }
    __syncthreads();
    // FF1 register-tiled
    {
        const float* W1 = w1 + l*16384;
        int rq = tid >> 6, jg = tid & 63;
        int j0 = jg*4;
        float4 bv = *(const float4*)(b1 + l*256 + j0);
        float acc[4][4];
        #pragma unroll
        for (int rr = 0; rr < 4; rr++) {
            acc[rr][0]=bv.x; acc[rr][1]=bv.y; acc[rr][2]=bv.z; acc[rr][3]=bv.w;
        }
        #pragma unroll 4
        for (int d = 0; d < 64; d++) {
            float4 wv = *(const float4*)(W1 + d*256 + j0);
            #pragma unroll
            for (int rr = 0; rr < 4; rr++) {
                float hv = hs[(rq*4+rr)*64 + d];
                acc[rr][0] += hv*wv.x; acc[rr][1] += hv*wv.y;
                acc[rr][2] += hv*wv.z; acc[rr][3] += hv*wv.w;
            }
        }
        #pragma unroll
        for (int rr = 0; rr < 4; rr++)
            #pragma unroll
            for (int jj = 0; jj < 4; jj++)
                hid[(rq*4+rr)*256 + j0 + jj] = fmaxf(acc[rr][jj], 0.0f);
    }
    __syncthreads();
    // FF2, 4-way j split
    {
        const float* W2 = w2 + l*16384;
        int dq = tid & 15, rq = (tid >> 4) & 3, js = tid >> 6;
        int d0 = dq*4, r0 = rq*4, j0 = js*64;
        float acc[4][4];
        #pragma unroll
        for (int rr = 0; rr < 4; rr++)
            #pragma unroll
            for (int dd = 0; dd < 4; dd++) acc[rr][dd] = 0.f;
        #pragma unroll 4
        for (int jj = 0; jj < 64; jj++) {
            int j = j0 + jj;
            float4 wv = *(const float4*)(W2 + j*64 + d0);
            #pragma unroll
            for (int rr = 0; rr < 4; rr++) {
                float hv = hid[(r0+rr)*256 + j];
                acc[rr][0] += hv*wv.x; acc[rr][1] += hv*wv.y;
                acc[rr][2] += hv*wv.z; acc[rr][3] += hv*wv.w;
            }
        }
        #pragma unroll
        for (int rr = 0; rr < 4; rr++)
            #pragma unroll
            for (int dd = 0; dd < 4; dd++)
                red[js*1024 + (r0+rr)*64 + d0+dd] = acc[rr][dd];
    }
    __syncthreads();
    for (int p = tid; p < 1024; p += 256) {
        int d = p & 63;
        ts[p] = red[p] + red[1024+p] + red[2048+p] + red[3072+p] + hs[p] + b2[l*64+d];
    }
    __syncthreads();
    // LN2 -> g_h
    {
        const float* s_ = ln2s + l*64; const float* b_ = ln2b + l*64;
        #pragma unroll
        for (int rr = 0; rr < 2; rr++) {
            int r = warp*2 + rr;
            float a = ts[r*64+lane], bv = ts[r*64+32+lane];
            float s = a + bv, qq = a*a + bv*bv;
            #pragma unroll
            for (int off = 16; off > 0; off >>= 1) {
                s  += __shfl_xor_sync(0xffffffff, s,  off);
                qq += __shfl_xor_sync(0xffffffff, qq, off);
            }
            float mu = s*(1.0f/64.0f);
            float var = qq*(1.0f/64.0f) - mu*mu;
            float rs = rsqrtf(var + 1e-5f);
            g_h[(row0+r)*64+lane]    = (a  - mu)*rs*s_[lane]    + b_[lane];
            g_h[(row0+r)*64+32+lane] = (bv - mu)*rs*s_[32+lane] + b_[32+lane];
        }
    }
}

// head: grid 32 (one block per sample), coalesced mean + argmax
__global__ __launch_bounds__(128) void k_head(const float* __restrict__ fcw,
                                              const float* __restrict__ fcb) {
    __shared__ float fe[128];
    int b = blockIdx.x;
    int t = threadIdx.x;
    int d = t & 63, sh = t >> 6;
    float acc = 0.f;
    for (int s = sh*64; s < sh*64 + 64; s++) acc += g_h[(b*128+s)*64 + d];
    fe[t] = acc;
    __syncthreads();
    if (t < 64) fe[t] = (fe[t] + fe[t+64])*(1.0f/128.0f);
    __syncthreads();
    if (t == 0) {
        float best = -1e30f; int bi = 0;
        for (int e = 0; e < En; e++) {
            float a = fcb[e];
            for (int dd = 0; dd < 64; dd++) a += fe[dd]*fcw[dd*En + e];
            if (a > best) { best = a; bi = e; }
        }
        g_idx[b] = bi;
    }
}

// ========================= FNO =========================

__global__ __launch_bounds__(256) void k_lift(const float* __restrict__ x,
                                              const float* __restrict__ lw,
                                              const float* __restrict__ lb) {
    __shared__ float xr[128];
    __shared__ float ws[32], bs[32];
    int bb = blockIdx.x >> 7, h = blockIdx.x & 127;
    int e = g_idx[bb];
    if (threadIdx.x < 128) xr[threadIdx.x] = x[bb*16384 + h*128 + threadIdx.x];
    if (threadIdx.x < 32) { ws[threadIdx.x] = lw[e*32+threadIdx.x]; bs[threadIdx.x] = lb[e*32+threadIdx.x]; }
    __syncthreads();
    for (int p = threadIdx.x; p < 4096; p += 256) {
        int d = p >> 7, w = p & 127;
        g_v[((bb*32+d)*128 + h)*128 + w] = xr[w]*ws[d] + bs[d];
    }
}

// fused 2D forward partial DFT per (b,c), with w-mirror and +/-kx symmetry.
__global__ __launch_bounds__(256) void k_dft2() {
    extern __shared__ float sm[];
    float*  vs = sm;                      // 8448
    float2* Az = (float2*)(sm + 8448);    // 2048 cplx
    float*  Tc = sm + 8448 + 4096;        // 1024
    float*  Ts = Tc + 1024;               // 1024
    float*  ct = Ts + 1024;               // 128
    float*  st = ct + 128;                // 128
    int bb = blockIdx.x >> 5, c = blockIdx.x & 31;
    int tid = threadIdx.x;
    if (tid < 128) {
        float ang = 6.283185307179586f*(float)tid/128.0f;
        ct[tid] = cosf(ang); st[tid] = sinf(ang);
    }
    for (int p = tid; p < 1024; p += 256) {
        int w = p >> 4, k = p & 15;
        int t = (w*k) & 127;
        float ang = 0.0490873852123405f*(float)t;
        Tc[p] = cosf(ang); Ts[p] = sinf(ang);
    }
    const float* vg = g_v + (bb*32 + c)*16384;
    int hl = tid >> 2, kq = tid & 3, ky0 = kq*4;
    for (int half = 0; half < 2; half++) {
        __syncthreads();
        for (int p = tid; p < 2048; p += 256) {
            int r = p >> 5, q = p & 31;
            ((float4*)(vs + r*132))[q] = ((const float4*)(vg + (half*64 + r)*128))[q];
        }
        __syncthreads();
        const float* vr = vs + hl*132;
        float v0 = vr[0], v64 = vr[64];
        float re[4], im[4];
        #pragma unroll
        for (int j = 0; j < 4; j++) {
            re[j] = v0 + (((ky0+j) & 1) ? -v64 : v64);
            im[j] = 0.f;
        }
        #pragma unroll 7
        for (int w = 1; w < 64; w++) {
            float a = vr[w], b = vr[128-w];
            float s_ = a + b, d_ = a - b;
            float4 c4 = *(const float4*)(Tc + w*16 + ky0);
            float4 s4 = *(const float4*)(Ts + w*16 + ky0);
            re[0] += s_*c4.x; im[0] -= d_*s4.x;
            re[1] += s_*c4.y; im[1] -= d_*s4.y;
            re[2] += s_*c4.z; im[2] -= d_*s4.z;
            re[3] += s_*c4.w; im[3] -= d_*s4.w;
        }
        #pragma unroll
        for (int j = 0; j < 4; j++)
            Az[(half*64 + hl)*16 + ky0 + j] = make_float2(re[j], im[j]);
    }
    __syncthreads();
    // stage 2: h-DFT with +/-kx pairing
    int g = tid >> 4, ky = tid & 15;
    if (g == 0) {
        float rex=0.f, imx=0.f, re16=0.f, im16=0.f;
        int t = 0;
        for (int h = 0; h < 128; h++) {
            float2 a = Az[h*16 + ky];
            rex += a.x; imx += a.y;
            float cc = ct[t], ss = st[t];
            re16 += a.x*cc - a.y*ss;   // kx = -16
            im16 += a.y*cc + a.x*ss;
            t = (t + 16) & 127;
        }
        g_X[((bb*32 + 0 )*16 + ky)*32 + c] = make_float2(rex,  imx);
        g_X[((bb*32 + 16)*16 + ky)*32 + c] = make_float2(re16, im16);
    } else {
        float u=0.f, v=0.f, pp=0.f, qq=0.f;
        int t = 0;
        for (int h = 0; h < 128; h++) {
            float2 a = Az[h*16 + ky];
            float cc = ct[t], ss = st[t];
            u  += a.x*cc; qq += a.x*ss;
            pp += a.y*cc; v  += a.y*ss;
            t = (t + g) & 127;
        }
        g_X[((bb*32 + g     )*16 + ky)*32 + c] = make_float2(u+v, pp-qq);
        g_X[((bb*32 + (32-g))*16 + ky)*32 + c] = make_float2(u-v, pp+qq);
    }
}

// spectral mix (unchanged)
__global__ __launch_bounds__(256) void k_mix(const float* __restrict__ wr,
                                             const float* __restrict__ wi, int l) {
    __shared__ float2 Xs[16*32];
    int bb = blockIdx.x >> 5, kxi = blockIdx.x & 31;
    int e = g_idx[bb];
    int r   = (kxi < 16) ? 0 : 1;
    int kxp = (kxi < 16) ? kxi : kxi - 16;
    const float2* src = g_X + ((bb*32 + kxi)*16)*32;
    for (int p = threadIdx.x; p < 512; p += 256) Xs[p] = src[p];
    __syncthreads();
    int base = ((e*4 + l)*2 + r)*(32*32*256);
    const float* wrb = wr + base + kxp*16;
    const float* wib = wi + base + kxp*16;
    for (int p = threadIdx.x; p < 512; p += 256) {
        int o = p >> 4, ky = p & 15;
        float re = 0.f, im = 0.f;
        #pragma unroll 8
        for (int i = 0; i < 32; i++) {
            float2 xv = Xs[ky*32 + i];
            float wre = wrb[i*8192 + o*256 + ky];
            float wim = wib[i*8192 + o*256 + ky];
            re += xv.x*wre - xv.y*wim;
            im += xv.x*wim + xv.y*wre;
        }
        g_Y[((bb*32 + o)*32 + kxi)*16 + ky] = make_float2(re, im);
    }
}

// inverse h-DFT with S/D symmetry: 17 paired terms instead of 32
__global__ __launch_bounds__(256) void k_idft2() {
    __shared__ __align__(16) float2 Ssm[17*16];
    __shared__ __align__(16) float2 Dsm[17*16];
    __shared__ float ct[128], st[128];
    int bb = blockIdx.x >> 5, o = blockIdx.x & 31;
    int tid = threadIdx.x;
    if (tid < 128) {
        float ang = 6.283185307179586f*(float)tid/128.0f;
        ct[tid] = cosf(ang); st[tid] = sinf(ang);
    }
    const float2* Yb = g_Y + ((bb*32 + o)*32)*16;  // [kxi][ky]
    for (int p = tid; p < 272; p += 256) {
        int g = p >> 4, ky = p & 15;
        float2 S, D;
        if (g == 0)      { S = Yb[ky]; D = make_float2(0.f, 0.f); }
        else if (g < 16) {
            float2 a = Yb[g*16 + ky], b = Yb[(32-g)*16 + ky];
            S = make_float2(a.x+b.x, a.y+b.y);
            D = make_float2(a.x-b.x, a.y-b.y);
        } else {
            float2 a = Yb[16*16 + ky];
            S = a; D = make_float2(-a.x, -a.y);
        }
        Ssm[p] = S; Dsm[p] = D;
    }
    __syncthreads();
    int h = tid >> 1, ky0 = (tid & 1)*8;
    float zr[8], zi[8];
    #pragma unroll
    for (int j = 0; j < 8; j++) { zr[j]=0.f; zi[j]=0.f; }
    #pragma unroll
    for (int g = 0; g <= 16; g++) {
        int t = (g*h) & 127;
        float cc = ct[t], ss = st[t];
        const float4* Sp = (const float4*)(Ssm + g*16 + ky0);
        const float4* Dp = (const float4*)(Dsm + g*16 + ky0);
        #pragma unroll
        for (int jj = 0; jj < 4; jj++) {
            float4 Sv = Sp[jj], Dv = Dp[jj];
            zr[jj*2]   += cc*Sv.x - ss*Dv.y;
            zi[jj*2]   += cc*Sv.y + ss*Dv.x;
            zr[jj*2+1] += cc*Sv.z - ss*Dv.w;
            zi[jj*2+1] += cc*Sv.w + ss*Dv.z;
        }
    }
    float2* dst = g_Z + ((bb*32 + o)*128 + h)*16 + ky0;
    #pragma unroll
    for (int j = 0; j < 8; j++) dst[j] = make_float2(zr[j], zi[j]);
}

// combine as one K=64 GEMM: rows 0..30 irfft-w twiddles (from g_Tw), 31..62 v, 63 ones*bias
// 256 threads, 4o x 4w per thread
__global__ __launch_bounds__(256) void k_comb64(const float* __restrict__ sw,
                                                const float* __restrict__ sb,
                                                int l, int last) {
    __shared__ __align__(16) float Bk[64*128];
    __shared__ __align__(16) float Ak[64*32];
    int bb = blockIdx.x >> 7, h = blockIdx.x & 127;
    int e = g_idx[bb];
    int tid = threadIdx.x;

    // Bk rows 0..30 (twiddles) + row 63 (ones) from g_Tw (row 31 of g_Tw = ones)
    for (int p = tid; p < 1024; p += 256) {
        int row = p >> 5, q = p & 31;
        int drow = (row == 31) ? 63 : row;
        ((float4*)(Bk + drow*128))[q] = ((const float4*)(g_Tw + row*128))[q];
    }
    // Bk rows 31..62: v
    for (int p = tid; p < 1024; p += 256) {
        int i = p >> 5, q = p & 31;
        ((float4*)(Bk + (31+i)*128))[q] = ((const float4*)(g_v + ((bb*32+i)*128+h)*128))[q];
    }
    // Ak Z rows (coalesced: ky fastest across lanes)
    for (int p = tid; p < 512; p += 256) {
        int o = p >> 4, ky = p & 15;
        float2 z = g_Z[((bb*32+o)*128+h)*16 + ky];
        const float s2 = 2.0f/16384.0f;
        if (ky == 0) Ak[o] = z.x*(1.0f/16384.0f);
        else { Ak[ky*32+o] = z.x*s2; Ak[(15+ky)*32+o] = -z.y*s2; }
    }
    // Ak skip rows
    for (int p = tid; p < 1024; p += 256)
        Ak[(31 + (p>>5))*32 + (p & 31)] = sw[(e*4+l)*1024 + p];
    // Ak bias row (pairs with ones row 63 of Bk)
    if (tid < 32) Ak[63*32 + tid] = sb[(e*4+l)*32 + tid];
    __syncthreads();

    int wg = tid & 31, og = tid >> 5;   // w = wg*4.., o = og*4..
    float acc[4][4];
    #pragma unroll
    for (int i = 0; i < 4; i++)
        #pragma unroll
        for (int j = 0; j < 4; j++) acc[i][j] = 0.f;
    #pragma unroll 8
    for (int k = 0; k < 64; k++) {
        float4 bv = ((const float4*)(Bk + k*128))[wg];
        float4 av = ((const float4*)(Ak + k*32))[og];
        acc[0][0]+=av.x*bv.x; acc[0][1]+=av.x*bv.y; acc[0][2]+=av.x*bv.z; acc[0][3]+=av.x*bv.w;
        acc[1][0]+=av.y*bv.x; acc[1][1]+=av.y*bv.y; acc[1][2]+=av.y*bv.z; acc[1][3]+=av.y*bv.w;
        acc[2][0]+=av.z*bv.x; acc[2][1]+=av.z*bv.y; acc[2][2]+=av.z*bv.z; acc[2][3]+=av.z*bv.w;
        acc[3][0]+=av.w*bv.x; acc[3][1]+=av.w*bv.y; acc[3][2]+=av.w*bv.z; acc[3][3]+=av.w*bv.w;
    }
    #pragma unroll
    for (int i = 0; i < 4; i++) {
        int o = og*4 + i;
        float v0 = acc[i][0], v1 = acc[i][1], v2 = acc[i][2], v3 = acc[i][3];
        if (!last) { v0 = gelu_tanh(v0); v1 = gelu_tanh(v1); v2 = gelu_tanh(v2); v3 = gelu_tanh(v3); }
        ((float4*)(g_v + ((bb*32+o)*128+h)*128))[wg] = make_float4(v0, v1, v2, v3);
    }
}

// projection (unchanged)
__global__ __launch_bounds__(256, 2) void k_proj2(
        const float* __restrict__ p1w, const float* __restrict__ p1b,
        const float* __restrict__ p2w, const float* __restrict__ p2b,
        float* __restrict__ out) {
    __shared__ float vs [32*128];
    __shared__ float w1p[32*128];
    __shared__ float red[16*128];
    __shared__ float b1s[128], p2s[128];
    int bb = blockIdx.x >> 7, h = blockIdx.x & 127;
    int e = g_idx[bb];
    int tid = threadIdx.x;
    #pragma unroll
    for (int j = 0; j < 4; j++) {
        int p = tid + 256*j;
        int i = p >> 5, q = p & 31;
        ((float4*)(vs + i*128))[q] = ((const float4*)(g_v + ((bb*32+i)*128+h)*128))[q];
    }
    for (int p = tid; p < 4096; p += 256) {
        float val = p1w[e*4096 + p];
        int c = p >> 7, pch = p & 127;
        w1p[c*128 + (pch & 15)*8 + (pch >> 4)] = val;
    }
    if (tid < 128) {
        b1s[tid] = p1b[e*128 + tid];
        p2s[tid] = p2w[e*128 + tid];
    }
    __syncthreads();

    int wg = tid & 15, pg = tid >> 4;
    int w0 = wg*8;
    float acc[8][8];
    #pragma unroll
    for (int i = 0; i < 8; i++)
        #pragma unroll
        for (int j = 0; j < 8; j++) acc[i][j] = 0.f;
    #pragma unroll 2
    for (int c = 0; c < 32; c++) {
        float4 v0 = ((const float4*)(vs + c*128 + w0))[0];
        float4 v1 = ((const float4*)(vs + c*128 + w0))[1];
        float4 u0 = ((const float4*)(w1p + c*128 + pg*8))[0];
        float4 u1 = ((const float4*)(w1p + c*128 + pg*8))[1];
        float vv[8] = {v0.x,v0.y,v0.z,v0.w,v1.x,v1.y,v1.z,v1.w};
        float uu[8] = {u0.x,u0.y,u0.z,u0.w,u1.x,u1.y,u1.z,u1.w};
        #pragma unroll
        for (int i = 0; i < 8; i++)
            #pragma unroll
            for (int j = 0; j < 8; j++)
                acc[i][j] += uu[i]*vv[j];
    }
    float part[8];
    #pragma unroll
    for (int j = 0; j < 8; j++) part[j] = 0.f;
    #pragma unroll
    for (int i = 0; i < 8; i++) {
        int pch = pg + 16*i;
        float bias = b1s[pch], p2v = p2s[pch];
        #pragma unroll
        for (int j = 0; j < 8; j++)
            part[j] += gelu_tanh(acc[i][j] + bias)*p2v;
    }
    #pragma unroll
    for (int j = 0; j < 8; j++) red[pg*128 + w0 + j] = part[j];
    __syncthreads();
    if (tid < 128) {
        int w = tid;
        float o = p2b[e];
        #pragma unroll
        for (int pg2 = 0; pg2 < 16; pg2++) o += red[pg2*128 + w];
        out[bb*16384 + h*128 + w] = o;
    }
}

// ========================= launch =========================
extern "C" void kernel_launch(void* const* d_in, const int* in_sizes, int n_in,
                              void* d_out, int out_size) {
    const float* x        = (const float*)d_in[0];
    const float* enc_in_w = (const float*)d_in[1];
    const float* enc_in_b = (const float*)d_in[2];
    const float* qkv_w    = (const float*)d_in[3];
    const float* qkv_b    = (const float*)d_in[4];
    const float* ao_w     = (const float*)d_in[5];
    const float* ao_b     = (const float*)d_in[6];
    const float* ln1_s    = (const float*)d_in[7];
    const float* ln1_b    = (const float*)d_in[8];
    const float* ff1_w    = (const float*)d_in[9];
    const float* ff1_b    = (const float*)d_in[10];
    const float* ff2_w    = (const float*)d_in[11];
    const float* ff2_b    = (const float*)d_in[12];
    const float* ln2_s    = (const float*)d_in[13];
    const float* ln2_b    = (const float*)d_in[14];
    const float* fc_w     = (const float*)d_in[15];
    const float* fc_b     = (const float*)d_in[16];
    const float* lift_w   = (const float*)d_in[17];
    const float* lift_b   = (const float*)d_in[18];
    const float* spec_wr  = (const float*)d_in[19];
    const float* spec_wi  = (const float*)d_in[20];
    const float* skip_w   = (const float*)d_in[21];
    const float* skip_b   = (const float*)d_in[22];
    const float* p1_w     = (const float*)d_in[23];
    const float* p1_b     = (const float*)d_in[24];
    const float* p2_w     = (const float*)d_in[25];
    const float* p2_b     = (const float*)d_in[26];

    cudaFuncSetAttribute(k_dft2, cudaFuncAttributeMaxDynamicSharedMemorySize, 59392);

    // twiddle table (idempotent)
    k_tw<<<32, 128>>>();

    // ---- router ----
    k_encode<<<256, 256>>>(x, enc_in_w, enc_in_b);
    for (int l = 0; l < NENCn; l++) {
        k_attn_qkv<<<Bn*NHn, 256>>>(qkv_w, qkv_b, l);
        k_plf<<<(Bn*Sn)/16, 256>>>(ao_w, ao_b, ln1_s, ln1_b,
                                   ff1_w, ff1_b, ff2_w, ff2_b, ln2_s, ln2_b, l);
    }
    k_head<<<Bn, 128>>>(fc_w, fc_b);

    // ---- FNO ----
    k_lift<<<Bn*Hn, 256>>>(x, lift_w, lift_b);
    for (int l = 0; l < NLn; l++) {
        k_dft2<<<Bn*CHn, 256, 59392>>>();
        k_mix<<<Bn*KXn, 256>>>(spec_wr, spec_wi, l);
        k_idft2<<<Bn*CHn, 256>>>();
        k_comb64<<<Bn*Hn, 256>>>(skip_w, skip_b, l, (l == NLn-1) ? 1 : 0);
    }
    k_proj2<<<Bn*Hn, 256>>>(p1_w, p1_b, p2_w, p2_b, (float*)d_out);
}